// round 6
// baseline (speedup 1.0000x reference)
#include <cuda_runtime.h>
#include <cuda_bf16.h>
#include <cstdint>
#include <math_constants.h>

// ---------------- problem constants ----------------
#define Bq 8
#define Nq 2048
#define Dq 512
#define Hq 512
#define ROWS (Bq * Nq)          // 16384

// ---------------- scratch (device globals) ----------------
__device__ __nv_bfloat16 g_xb[(size_t)ROWS * Dq];
__device__ __nv_bfloat16 g_qb[(size_t)ROWS * Hq];
__device__ __nv_bfloat16 g_kb[(size_t)ROWS * Hq];
__device__ __nv_bfloat16 g_vTb[(size_t)Hq * ROWS];
__device__ __nv_bfloat16 g_ctxb[(size_t)ROWS * Hq];
__device__ __nv_bfloat16 g_attnb[(size_t)Bq * Nq * Nq];  // scores then probs (bf16)
__device__ __nv_bfloat16 g_wtb[(size_t)4 * Dq * Hq];     // WqT, WkT, WvT, WoT
__device__ float g_tmp[(size_t)ROWS * Dq];               // pre-LN (fp32)

// ---------------- helpers ----------------
__device__ __forceinline__ uint32_t smem_u32(const void* p) {
    uint32_t a;
    asm("{ .reg .u64 t; cvta.to.shared.u64 t, %1; cvt.u32.u64 %0, t; }" : "=r"(a) : "l"(p));
    return a;
}
#define LDSM_X4(r0, r1, r2, r3, addr) \
    asm volatile("ldmatrix.sync.aligned.m8n8.x4.shared.b16 {%0,%1,%2,%3}, [%4];" \
        : "=r"(r0), "=r"(r1), "=r"(r2), "=r"(r3) : "r"(addr))
#define CP_ASYNC16(dst, src) \
    asm volatile("cp.async.cg.shared.global [%0], [%1], 16;" :: "r"(dst), "l"(src))
#define CP_COMMIT() asm volatile("cp.async.commit_group;" ::: "memory")
#define CP_WAIT(n)  asm volatile("cp.async.wait_group %0;" :: "n"(n) : "memory")

__device__ __forceinline__ void mma_bf16(float* d, const uint32_t* a,
                                         uint32_t b0, uint32_t b1) {
    asm volatile(
        "mma.sync.aligned.m16n8k16.row.col.f32.bf16.bf16.f32 "
        "{%0,%1,%2,%3}, {%4,%5,%6,%7}, {%8,%9}, {%0,%1,%2,%3};"
        : "+f"(d[0]), "+f"(d[1]), "+f"(d[2]), "+f"(d[3])
        : "r"(a[0]), "r"(a[1]), "r"(a[2]), "r"(a[3]), "r"(b0), "r"(b1));
}

// ---------------- bf16 mma.sync GEMM, cp.async 4-stage ----------------
// C[M,N] = alpha * A[M,K] @ B[N,K]^T (+ bias) (+ res). A,B bf16 K-major.
// BIASMODE: 0 none, 1 bias[col], 2 bias[row]. OUTBF16: C bf16 else fp32.
// CTA tile 256x128x32; 256 threads; 8 warps (4 M x 2 N), warp tile 64x64.
// SMEM rows: 32 bf16 (64 B) padded to 80 B -> conflict-free ldmatrix.
#define BM_T 256
#define BN_T 128
#define RPAD_B 80
#define A_BYTES (BM_T * RPAD_B)                   // 20480
#define B_BYTES (BN_T * RPAD_B)                   // 10240
#define STAGE_T (A_BYTES + B_BYTES)               // 30720
#define NSTAGE 4
#define SMEM_TOTAL (NSTAGE * STAGE_T)             // 122880 (dynamic)

template<int BIASMODE, bool RES, bool OUTBF16>
__global__ __launch_bounds__(256, 1) void mma_gemm(
    const __nv_bfloat16* __restrict__ A, const __nv_bfloat16* __restrict__ B,
    const float* __restrict__ bias, const float* __restrict__ resid,
    void* __restrict__ Cv,
    int K, int lda, int ldb, int ldc,
    long long sA, long long sB, long long sC, float alpha)
{
    extern __shared__ char smem[];
    const uint32_t sb = smem_u32(smem);
    const int tid = threadIdx.x;
    const int wid = tid >> 5;
    const int l   = tid & 31;
    const int wm  = wid >> 1;             // 0..3  (M)
    const int wn  = wid & 1;              // 0..1  (N)
    const int bz  = blockIdx.z;
    const int row0 = blockIdx.y * BM_T;
    const int col0 = blockIdx.x * BN_T;

    A += (long long)bz * sA + (long long)row0 * lda;
    B += (long long)bz * sB + (long long)col0 * ldb;
    const long long cbase = (long long)bz * sC + (long long)row0 * ldc + col0;
    const float* Rp = RES ? (resid + cbase) : nullptr;

    // ---- cp.async mapping: 6 x 16B per thread per stage (4 A, 2 B)
    const int r0  = tid >> 2;             // 0..63 (+64 per chunk)
    const int c16 = tid & 3;              // 16B column within 64B k-row
    const __nv_bfloat16* Ag = A + (long long)r0 * lda + c16 * 8;
    const __nv_bfloat16* Bg = B + (long long)r0 * ldb + c16 * 8;
    const uint32_t dstA = sb + (uint32_t)(r0 * RPAD_B + c16 * 16);
    const uint32_t dstB = dstA + A_BYTES;

    // ---- ldmatrix lane addresses (within-stage offsets)
    const uint32_t a_off = sb
        + (uint32_t)((wm * 64 + (l & 15)) * RPAD_B + ((l >> 4) & 1) * 16);
    const uint32_t b_off = sb + A_BYTES
        + (uint32_t)((wn * 64 + (l & 15)) * RPAD_B + ((l >> 4) & 1) * 16);

    float acc[4][8][4];
#pragma unroll
    for (int mt = 0; mt < 4; mt++)
#pragma unroll
        for (int nt = 0; nt < 8; nt++)
#pragma unroll
            for (int i = 0; i < 4; i++) acc[mt][nt][i] = 0.f;

    auto issue_stage = [&](int s) {
        const int buf = s & (NSTAGE - 1);
        const __nv_bfloat16* ap = Ag + s * 32;
        const __nv_bfloat16* bp = Bg + s * 32;
        const uint32_t da = dstA + buf * STAGE_T;
        const uint32_t db = dstB + buf * STAGE_T;
#pragma unroll
        for (int i = 0; i < 4; i++)
            CP_ASYNC16(da + i * 64 * RPAD_B, ap + (long long)(64 * i) * lda);
#pragma unroll
        for (int i = 0; i < 2; i++)
            CP_ASYNC16(db + i * 64 * RPAD_B, bp + (long long)(64 * i) * ldb);
    };
    auto compute_stage = [&](int buf) {
        const uint32_t ab = a_off + buf * STAGE_T;
        const uint32_t bb = b_off + buf * STAGE_T;
#pragma unroll
        for (int kb = 0; kb < 2; kb++) {
            uint32_t afr[4][4], bfr[4][4];
#pragma unroll
            for (int mt = 0; mt < 4; mt++)
                LDSM_X4(afr[mt][0], afr[mt][1], afr[mt][2], afr[mt][3],
                        ab + mt * (16 * RPAD_B) + kb * 32);
#pragma unroll
            for (int t = 0; t < 4; t++)
                LDSM_X4(bfr[t][0], bfr[t][1], bfr[t][2], bfr[t][3],
                        bb + t * (16 * RPAD_B) + kb * 32);
#pragma unroll
            for (int mt = 0; mt < 4; mt++)
#pragma unroll
                for (int nt = 0; nt < 8; nt++)
                    mma_bf16(acc[mt][nt], afr[mt],
                             bfr[nt >> 1][nt & 1], bfr[nt >> 1][2 + (nt & 1)]);
        }
    };

    const int nst = K >> 5;
#pragma unroll
    for (int s = 0; s < NSTAGE - 1; s++) { issue_stage(s); CP_COMMIT(); }
    for (int s = 0; s < nst; s++) {
        CP_WAIT(NSTAGE - 2);
        __syncthreads();
        if (s + NSTAGE - 1 < nst) issue_stage(s + NSTAGE - 1);
        CP_COMMIT();
        compute_stage(s & (NSTAGE - 1));
    }

    // ---- epilogue
    float* Cf = (float*)Cv;
    __nv_bfloat16* Cb = (__nv_bfloat16*)Cv;
    const int lr  = l >> 2;
    const int lc2 = (l & 3) * 2;
#pragma unroll
    for (int mt = 0; mt < 4; mt++) {
        const int rA = wm * 64 + mt * 16 + lr;
        float blo = 0.f, bhi = 0.f;
        if (BIASMODE == 2) { blo = bias[row0 + rA]; bhi = bias[row0 + rA + 8]; }
#pragma unroll
        for (int nt = 0; nt < 8; nt++) {
            const int cA = wn * 64 + nt * 8 + lc2;
            float2 v0, v1;
            v0.x = acc[mt][nt][0] * alpha; v0.y = acc[mt][nt][1] * alpha;
            v1.x = acc[mt][nt][2] * alpha; v1.y = acc[mt][nt][3] * alpha;
            if (BIASMODE == 1) {
                float2 bb2 = *(const float2*)(bias + col0 + cA);
                v0.x += bb2.x; v0.y += bb2.y; v1.x += bb2.x; v1.y += bb2.y;
            } else if (BIASMODE == 2) {
                v0.x += blo; v0.y += blo; v1.x += bhi; v1.y += bhi;
            }
            if (RES) {
                float2 q0 = *(const float2*)(Rp + (long long)rA * ldc + cA);
                float2 q1 = *(const float2*)(Rp + (long long)(rA + 8) * ldc + cA);
                v0.x += q0.x; v0.y += q0.y; v1.x += q1.x; v1.y += q1.y;
            }
            if (OUTBF16) {
                *(__nv_bfloat162*)(Cb + cbase + (long long)rA * ldc + cA) =
                    __float22bfloat162_rn(v0);
                *(__nv_bfloat162*)(Cb + cbase + (long long)(rA + 8) * ldc + cA) =
                    __float22bfloat162_rn(v1);
            } else {
                *(float2*)(Cf + cbase + (long long)rA * ldc + cA) = v0;
                *(float2*)(Cf + cbase + (long long)(rA + 8) * ldc + cA) = v1;
            }
        }
    }
}

// ---------------- X -> bf16 ----------------
__global__ __launch_bounds__(256) void cvt_x_k(const float* __restrict__ X,
                                               __nv_bfloat16* __restrict__ Xb)
{
    const size_t i = ((size_t)blockIdx.x * 256 + threadIdx.x) * 4;
    float4 v = *(const float4*)(X + i);
    *(__nv_bfloat162*)(Xb + i)     = __float22bfloat162_rn(make_float2(v.x, v.y));
    *(__nv_bfloat162*)(Xb + i + 2) = __float22bfloat162_rn(make_float2(v.z, v.w));
}

// ---------------- weight transpose -> bf16: WT[n,k] = W[k,n] ----------------
__global__ __launch_bounds__(256) void transpose4_k(
    const float* __restrict__ w0, const float* __restrict__ w1,
    const float* __restrict__ w2, const float* __restrict__ w3,
    __nv_bfloat16* __restrict__ out)
{
    __shared__ float t[32][33];
    const int z = blockIdx.z;
    const float* W = (z == 0) ? w0 : (z == 1) ? w1 : (z == 2) ? w2 : w3;
    __nv_bfloat16* O = out + (size_t)z * Dq * Hq;
    const int tx = threadIdx.x & 31;
    const int ty = threadIdx.x >> 5;
    const int x = blockIdx.x * 32 + tx;
    const int y0 = blockIdx.y * 32;
#pragma unroll
    for (int i = ty; i < 32; i += 8) t[i][tx] = W[(y0 + i) * Hq + x];
    __syncthreads();
    const int ox = blockIdx.y * 32 + tx;
#pragma unroll
    for (int i = ty; i < 32; i += 8)
        O[(blockIdx.x * 32 + i) * Dq + ox] = __float2bfloat16_rn(t[tx][i]);
}

// ---------------- softmax in-place on bf16 rows of [16384][2048] ----------------
__global__ __launch_bounds__(256) void softmax_k(__nv_bfloat16* __restrict__ S)
{
    __shared__ float red[256];
    __nv_bfloat16* p = S + blockIdx.x * (long long)Nq;
    const int t = threadIdx.x;

    uint4 raw = *(const uint4*)(p + t * 8);
    const __nv_bfloat162* h2 = (const __nv_bfloat162*)&raw;
    float v[8];
#pragma unroll
    for (int i = 0; i < 4; i++) {
        float2 f = __bfloat1622float2(h2[i]);
        v[2 * i] = f.x; v[2 * i + 1] = f.y;
    }
    float mx = v[0];
#pragma unroll
    for (int i = 1; i < 8; i++) mx = fmaxf(mx, v[i]);
    red[t] = mx; __syncthreads();
    for (int s = 128; s > 0; s >>= 1) { if (t < s) red[t] = fmaxf(red[t], red[t + s]); __syncthreads(); }
    const float m = red[0]; __syncthreads();
    float sum = 0.f;
#pragma unroll
    for (int i = 0; i < 8; i++) { v[i] = __expf(v[i] - m); sum += v[i]; }
    red[t] = sum; __syncthreads();
    for (int s = 128; s > 0; s >>= 1) { if (t < s) red[t] += red[t + s]; __syncthreads(); }
    const float inv = 1.f / red[0];
    uint4 outw;
    __nv_bfloat162* o2 = (__nv_bfloat162*)&outw;
#pragma unroll
    for (int i = 0; i < 4; i++)
        o2[i] = __float22bfloat162_rn(make_float2(v[2 * i] * inv, v[2 * i + 1] * inv));
    *(uint4*)(p + t * 8) = outw;
}

// ---------------- LayerNorm over last dim (512) ----------------
__global__ __launch_bounds__(256) void ln_k(
    const float* __restrict__ in, const float* __restrict__ gamma,
    const float* __restrict__ beta, float* __restrict__ out)
{
    __shared__ float red[256];
    const float* p = in + blockIdx.x * (long long)Dq;
    const int t = threadIdx.x;
    float a = p[t], b = p[t + 256];
    red[t] = a + b; __syncthreads();
    for (int s = 128; s > 0; s >>= 1) { if (t < s) red[t] += red[t + s]; __syncthreads(); }
    const float mu = red[0] * (1.f / Dq); __syncthreads();
    float da = a - mu, db = b - mu;
    red[t] = da * da + db * db; __syncthreads();
    for (int s = 128; s > 0; s >>= 1) { if (t < s) red[t] += red[t + s]; __syncthreads(); }
    const float inv = rsqrtf(red[0] * (1.f / Dq) + 1e-5f);
    out[blockIdx.x * (long long)Dq + t]       = da * inv * gamma[t]       + beta[t];
    out[blockIdx.x * (long long)Dq + t + 256] = db * inv * gamma[t + 256] + beta[t + 256];
}

// ---------------- launch ----------------
extern "C" void kernel_launch(void* const* d_in, const int* in_sizes, int n_in,
                              void* d_out, int out_size)
{
    const float* X   = (const float*)d_in[0];
    const float* Wq  = (const float*)d_in[1];
    const float* bqp = (const float*)d_in[2];
    const float* Wk  = (const float*)d_in[3];
    const float* bkp = (const float*)d_in[4];
    const float* Wv  = (const float*)d_in[5];
    const float* bvp = (const float*)d_in[6];
    const float* Wo  = (const float*)d_in[7];
    const float* bop = (const float*)d_in[8];
    const float* ga  = (const float*)d_in[9];
    const float* be  = (const float*)d_in[10];
    float* out = (float*)d_out;

    void *pxb, *pqb, *pkb, *pvTb, *pctxb, *pattnb, *pwtb, *ptmp;
    cudaGetSymbolAddress(&pxb, g_xb);
    cudaGetSymbolAddress(&pqb, g_qb);
    cudaGetSymbolAddress(&pkb, g_kb);
    cudaGetSymbolAddress(&pvTb, g_vTb);
    cudaGetSymbolAddress(&pctxb, g_ctxb);
    cudaGetSymbolAddress(&pattnb, g_attnb);
    cudaGetSymbolAddress(&pwtb, g_wtb);
    cudaGetSymbolAddress(&ptmp, g_tmp);
    __nv_bfloat16* xb    = (__nv_bfloat16*)pxb;
    __nv_bfloat16* qb    = (__nv_bfloat16*)pqb;
    __nv_bfloat16* kb    = (__nv_bfloat16*)pkb;
    __nv_bfloat16* vTb   = (__nv_bfloat16*)pvTb;
    __nv_bfloat16* ctxb  = (__nv_bfloat16*)pctxb;
    __nv_bfloat16* attnb = (__nv_bfloat16*)pattnb;
    __nv_bfloat16* wtb   = (__nv_bfloat16*)pwtb;
    float* tmp = (float*)ptmp;
    __nv_bfloat16* WqT = wtb;
    __nv_bfloat16* WkT = wtb + (size_t)Dq * Hq;
    __nv_bfloat16* WvT = wtb + (size_t)2 * Dq * Hq;
    __nv_bfloat16* WoT = wtb + (size_t)3 * Dq * Hq;

    cudaFuncSetAttribute(mma_gemm<1, false, true>, cudaFuncAttributeMaxDynamicSharedMemorySize, SMEM_TOTAL);
    cudaFuncSetAttribute(mma_gemm<2, false, true>, cudaFuncAttributeMaxDynamicSharedMemorySize, SMEM_TOTAL);
    cudaFuncSetAttribute(mma_gemm<0, false, true>, cudaFuncAttributeMaxDynamicSharedMemorySize, SMEM_TOTAL);
    cudaFuncSetAttribute(mma_gemm<1, true, false>, cudaFuncAttributeMaxDynamicSharedMemorySize, SMEM_TOTAL);

    const float inv_sqrt_h = 0.04419417382415922f;  // 1/sqrt(512)
    dim3 blk(256);

    // 0. convert X; transpose+convert weights
    cvt_x_k<<<(ROWS * Dq) / (256 * 4), blk>>>(X, xb);
    transpose4_k<<<dim3(16, 16, 4), blk>>>(Wq, Wk, Wv, Wo, wtb);

    // 1. q = X @ Wq + bq  (bf16)
    mma_gemm<1, false, true><<<dim3(Hq / BN_T, ROWS / BM_T, 1), blk, SMEM_TOTAL>>>(
        xb, WqT, bqp, nullptr, qb, Dq, Dq, Dq, Hq, 0, 0, 0, 1.f);
    // 2. k = X @ Wk + bk  (bf16)
    mma_gemm<1, false, true><<<dim3(Hq / BN_T, ROWS / BM_T, 1), blk, SMEM_TOTAL>>>(
        xb, WkT, bkp, nullptr, kb, Dq, Dq, Dq, Hq, 0, 0, 0, 1.f);
    // 3. vT[h,n] = Wv[:,h].X[n,:] + bv[h]  (bf16, row bias)
    mma_gemm<2, false, true><<<dim3(ROWS / BN_T, Hq / BM_T, 1), blk, SMEM_TOTAL>>>(
        WvT, xb, bvp, nullptr, vTb, Dq, Dq, Dq, ROWS, 0, 0, 0, 1.f);
    // 4. scores = q @ k^T / sqrt(H)  (bf16 out, batched)
    mma_gemm<0, false, true><<<dim3(Nq / BN_T, Nq / BM_T, Bq), blk, SMEM_TOTAL>>>(
        qb, kb, nullptr, nullptr, attnb, Hq, Hq, Hq, Nq,
        (long long)Nq * Hq, (long long)Nq * Hq, (long long)Nq * Nq, inv_sqrt_h);
    // 5. softmax in place (bf16)
    softmax_k<<<ROWS, blk>>>(attnb);
    // 6. ctx = attn @ v  (bf16)
    mma_gemm<0, false, true><<<dim3(Hq / BN_T, Nq / BM_T, Bq), blk, SMEM_TOTAL>>>(
        attnb, vTb, nullptr, nullptr, ctxb, Nq, Nq, ROWS, Hq,
        (long long)Nq * Nq, (long long)Nq, (long long)Nq * Hq, 1.f);
    // 7. out_pre = ctx @ Wo + bo + X  (fp32)
    mma_gemm<1, true, false><<<dim3(Dq / BN_T, ROWS / BM_T, 1), blk, SMEM_TOTAL>>>(
        ctxb, WoT, bop, X, tmp, Hq, Hq, Hq, Dq, 0, 0, 0, 1.f);
    // 8. LayerNorm
    ln_k<<<ROWS, blk>>>(tmp, ga, be, out);
}

// round 7
// speedup vs baseline: 1.0425x; 1.0425x over previous
#include <cuda_runtime.h>
#include <cuda_bf16.h>
#include <cuda_fp8.h>
#include <cstdint>
#include <math_constants.h>

// ---------------- problem constants ----------------
#define Bq 8
#define Nq 2048
#define Dq 512
#define Hq 512
#define ROWS (Bq * Nq)          // 16384

// ---------------- scratch (device globals) ----------------
__device__ __nv_bfloat16 g_xb[(size_t)ROWS * Dq];
__device__ uint8_t g_q8[(size_t)ROWS * Hq];
__device__ uint8_t g_k8[(size_t)ROWS * Hq];
__device__ uint8_t g_v8T[(size_t)Hq * ROWS];             // v fp8, transposed [H, B*N]
__device__ uint8_t g_p8[(size_t)Bq * Nq * Nq];           // probs fp8 (x256)
__device__ __nv_bfloat16 g_attnb[(size_t)Bq * Nq * Nq];  // scores bf16
__device__ __nv_bfloat16 g_ctxb[(size_t)ROWS * Hq];
__device__ __nv_bfloat16 g_wtb[(size_t)4 * Dq * Hq];     // WqT, WkT, WvT, WoT
__device__ float g_tmp[(size_t)ROWS * Dq];               // pre-LN (fp32)

// ---------------- helpers ----------------
__device__ __forceinline__ uint32_t smem_u32(const void* p) {
    uint32_t a;
    asm("{ .reg .u64 t; cvta.to.shared.u64 t, %1; cvt.u32.u64 %0, t; }" : "=r"(a) : "l"(p));
    return a;
}
#define LDSM_X4(r0, r1, r2, r3, addr) \
    asm volatile("ldmatrix.sync.aligned.m8n8.x4.shared.b16 {%0,%1,%2,%3}, [%4];" \
        : "=r"(r0), "=r"(r1), "=r"(r2), "=r"(r3) : "r"(addr))
#define CP_ASYNC16(dst, src) \
    asm volatile("cp.async.cg.shared.global [%0], [%1], 16;" :: "r"(dst), "l"(src))
#define CP_COMMIT() asm volatile("cp.async.commit_group;" ::: "memory")
#define CP_WAIT(n)  asm volatile("cp.async.wait_group %0;" :: "n"(n) : "memory")

__device__ __forceinline__ void mma_bf16(float* d, const uint32_t* a,
                                         uint32_t b0, uint32_t b1) {
    asm volatile(
        "mma.sync.aligned.m16n8k16.row.col.f32.bf16.bf16.f32 "
        "{%0,%1,%2,%3}, {%4,%5,%6,%7}, {%8,%9}, {%0,%1,%2,%3};"
        : "+f"(d[0]), "+f"(d[1]), "+f"(d[2]), "+f"(d[3])
        : "r"(a[0]), "r"(a[1]), "r"(a[2]), "r"(a[3]), "r"(b0), "r"(b1));
}
__device__ __forceinline__ void mma_fp8(float* d, const uint32_t* a,
                                        uint32_t b0, uint32_t b1) {
    asm volatile(
        "mma.sync.aligned.m16n8k32.row.col.f32.e4m3.e4m3.f32 "
        "{%0,%1,%2,%3}, {%4,%5,%6,%7}, {%8,%9}, {%0,%1,%2,%3};"
        : "+f"(d[0]), "+f"(d[1]), "+f"(d[2]), "+f"(d[3])
        : "r"(a[0]), "r"(a[1]), "r"(a[2]), "r"(a[3]), "r"(b0), "r"(b1));
}
__device__ __forceinline__ uint16_t f2_to_fp8x2(float x, float y) {
    return (uint16_t)__nv_cvt_float2_to_fp8x2(make_float2(x, y),
                                              __NV_SATFINITE, __NV_E4M3);
}

// ---------------- shared tiling constants ----------------
// Both GEMMs: CTA tile 128x128; 256 threads; 8 warps (2 M x 4 N), warp 64x32.
// SMEM rows: 64 bytes payload padded to 80 B -> conflict-free ldmatrix.
// bf16: 64B row = 32 elements (k-stage 32). fp8: 64B row = 64 elements (k-stage 64).
#define RPAD_B 80
#define HALF_B (128 * RPAD_B)                     // 10240 per operand per stage
#define STAGE_T (2 * HALF_B)                      // 20480 (A + B)
#define NSTAGE 4
#define SMEM_TOTAL (NSTAGE * STAGE_T)             // 81920 (dynamic)

// ===================== bf16 GEMM =====================
// C[M,N] = alpha * A[M,K] @ B[N,K]^T (+ bias) (+ res). A,B bf16 K-major.
// BIASMODE: 0 none, 1 bias[col], 2 bias[row]. OUTMODE: 0 f32, 1 bf16, 2 fp8.
template<int BIASMODE, bool RES, int OUTMODE>
__global__ __launch_bounds__(256) void mma_gemm(
    const __nv_bfloat16* __restrict__ A, const __nv_bfloat16* __restrict__ B,
    const float* __restrict__ bias, const float* __restrict__ resid,
    void* __restrict__ Cv,
    int K, int lda, int ldb, int ldc,
    long long sA, long long sB, long long sC, float alpha)
{
    extern __shared__ char smem[];
    const uint32_t sb = smem_u32(smem);
    const int tid = threadIdx.x;
    const int wid = tid >> 5;
    const int l   = tid & 31;
    const int wm  = wid & 1;
    const int wn  = wid >> 1;
    const int bz  = blockIdx.z;
    const int row0 = blockIdx.y * 128;
    const int col0 = blockIdx.x * 128;

    A += (long long)bz * sA + (long long)row0 * lda;
    B += (long long)bz * sB + (long long)col0 * ldb;
    const long long cbase = (long long)bz * sC + (long long)row0 * ldc + col0;
    const float* Rp = RES ? (resid + cbase) : nullptr;

    const int r0  = tid >> 2;
    const int c16 = tid & 3;
    const __nv_bfloat16* Ag = A + (long long)r0 * lda + c16 * 8;
    const __nv_bfloat16* Bg = B + (long long)r0 * ldb + c16 * 8;
    const uint32_t dstA = sb + (uint32_t)(r0 * RPAD_B + c16 * 16);
    const uint32_t dstB = dstA + HALF_B;

    const uint32_t a_off = sb
        + (uint32_t)((wm * 64 + (l & 15)) * RPAD_B + ((l >> 4) & 1) * 16);
    const uint32_t b_off = sb + HALF_B
        + (uint32_t)((wn * 32 + (l & 15)) * RPAD_B + ((l >> 4) & 1) * 16);

    float acc[4][4][4];
#pragma unroll
    for (int mt = 0; mt < 4; mt++)
#pragma unroll
        for (int nt = 0; nt < 4; nt++)
#pragma unroll
            for (int i = 0; i < 4; i++) acc[mt][nt][i] = 0.f;

    auto issue_stage = [&](int s) {
        const int buf = s & (NSTAGE - 1);
        const __nv_bfloat16* ap = Ag + s * 32;
        const __nv_bfloat16* bp = Bg + s * 32;
        const uint32_t da = dstA + buf * STAGE_T;
        const uint32_t db = dstB + buf * STAGE_T;
#pragma unroll
        for (int i = 0; i < 2; i++) {
            CP_ASYNC16(da + i * 64 * RPAD_B, ap + (long long)(64 * i) * lda);
            CP_ASYNC16(db + i * 64 * RPAD_B, bp + (long long)(64 * i) * ldb);
        }
    };
    auto compute_stage = [&](int buf) {
        const uint32_t ab = a_off + buf * STAGE_T;
        const uint32_t bb = b_off + buf * STAGE_T;
#pragma unroll
        for (int kb = 0; kb < 2; kb++) {
            uint32_t afr[4][4], bfr[2][4];
#pragma unroll
            for (int mt = 0; mt < 4; mt++)
                LDSM_X4(afr[mt][0], afr[mt][1], afr[mt][2], afr[mt][3],
                        ab + mt * (16 * RPAD_B) + kb * 32);
#pragma unroll
            for (int t = 0; t < 2; t++)
                LDSM_X4(bfr[t][0], bfr[t][1], bfr[t][2], bfr[t][3],
                        bb + t * (16 * RPAD_B) + kb * 32);
#pragma unroll
            for (int mt = 0; mt < 4; mt++)
#pragma unroll
                for (int nt = 0; nt < 4; nt++)
                    mma_bf16(acc[mt][nt], afr[mt],
                             bfr[nt >> 1][nt & 1], bfr[nt >> 1][2 + (nt & 1)]);
        }
    };

    const int nst = K >> 5;
#pragma unroll
    for (int s = 0; s < NSTAGE - 1; s++) { issue_stage(s); CP_COMMIT(); }
    for (int s = 0; s < nst; s++) {
        CP_WAIT(NSTAGE - 2);
        __syncthreads();
        if (s + NSTAGE - 1 < nst) issue_stage(s + NSTAGE - 1);
        CP_COMMIT();
        compute_stage(s & (NSTAGE - 1));
    }

    // ---- epilogue
    float* Cf = (float*)Cv;
    __nv_bfloat16* Cb = (__nv_bfloat16*)Cv;
    uint8_t* C8 = (uint8_t*)Cv;
    const int lr  = l >> 2;
    const int lc2 = (l & 3) * 2;
#pragma unroll
    for (int mt = 0; mt < 4; mt++) {
        const int rA = wm * 64 + mt * 16 + lr;
        float blo = 0.f, bhi = 0.f;
        if (BIASMODE == 2) { blo = bias[row0 + rA]; bhi = bias[row0 + rA + 8]; }
#pragma unroll
        for (int nt = 0; nt < 4; nt++) {
            const int cA = wn * 32 + nt * 8 + lc2;
            float2 v0, v1;
            v0.x = acc[mt][nt][0] * alpha; v0.y = acc[mt][nt][1] * alpha;
            v1.x = acc[mt][nt][2] * alpha; v1.y = acc[mt][nt][3] * alpha;
            if (BIASMODE == 1) {
                float2 bb2 = *(const float2*)(bias + col0 + cA);
                v0.x += bb2.x; v0.y += bb2.y; v1.x += bb2.x; v1.y += bb2.y;
            } else if (BIASMODE == 2) {
                v0.x += blo; v0.y += blo; v1.x += bhi; v1.y += bhi;
            }
            if (RES) {
                float2 q0 = *(const float2*)(Rp + (long long)rA * ldc + cA);
                float2 q1 = *(const float2*)(Rp + (long long)(rA + 8) * ldc + cA);
                v0.x += q0.x; v0.y += q0.y; v1.x += q1.x; v1.y += q1.y;
            }
            if (OUTMODE == 1) {
                *(__nv_bfloat162*)(Cb + cbase + (long long)rA * ldc + cA) =
                    __float22bfloat162_rn(v0);
                *(__nv_bfloat162*)(Cb + cbase + (long long)(rA + 8) * ldc + cA) =
                    __float22bfloat162_rn(v1);
            } else if (OUTMODE == 2) {
                *(uint16_t*)(C8 + cbase + (long long)rA * ldc + cA) =
                    f2_to_fp8x2(v0.x, v0.y);
                *(uint16_t*)(C8 + cbase + (long long)(rA + 8) * ldc + cA) =
                    f2_to_fp8x2(v1.x, v1.y);
            } else {
                *(float2*)(Cf + cbase + (long long)rA * ldc + cA) = v0;
                *(float2*)(Cf + cbase + (long long)(rA + 8) * ldc + cA) = v1;
            }
        }
    }
}

// ===================== fp8 GEMM =====================
// C[M,N] = alpha * A[M,K] @ B[N,K]^T, A,B e4m3 K-major, C bf16.
// Same tiling; 64-element (64 B) k-stages; fragment byte-layout identical to bf16.
__global__ __launch_bounds__(256) void mma_gemm_f8(
    const uint8_t* __restrict__ A, const uint8_t* __restrict__ B,
    __nv_bfloat16* __restrict__ C,
    int K, int lda, int ldb, int ldc,
    long long sA, long long sB, long long sC, float alpha)
{
    extern __shared__ char smem[];
    const uint32_t sb = smem_u32(smem);
    const int tid = threadIdx.x;
    const int wid = tid >> 5;
    const int l   = tid & 31;
    const int wm  = wid & 1;
    const int wn  = wid >> 1;
    const int bz  = blockIdx.z;
    const int row0 = blockIdx.y * 128;
    const int col0 = blockIdx.x * 128;

    A += (long long)bz * sA + (long long)row0 * lda;
    B += (long long)bz * sB + (long long)col0 * ldb;
    const long long cbase = (long long)bz * sC + (long long)row0 * ldc + col0;

    const int r0  = tid >> 2;
    const int c16 = tid & 3;
    const uint8_t* Ag = A + (long long)r0 * lda + c16 * 16;
    const uint8_t* Bg = B + (long long)r0 * ldb + c16 * 16;
    const uint32_t dstA = sb + (uint32_t)(r0 * RPAD_B + c16 * 16);
    const uint32_t dstB = dstA + HALF_B;

    const uint32_t a_off = sb
        + (uint32_t)((wm * 64 + (l & 15)) * RPAD_B + ((l >> 4) & 1) * 16);
    const uint32_t b_off = sb + HALF_B
        + (uint32_t)((wn * 32 + (l & 15)) * RPAD_B + ((l >> 4) & 1) * 16);

    float acc[4][4][4];
#pragma unroll
    for (int mt = 0; mt < 4; mt++)
#pragma unroll
        for (int nt = 0; nt < 4; nt++)
#pragma unroll
            for (int i = 0; i < 4; i++) acc[mt][nt][i] = 0.f;

    auto issue_stage = [&](int s) {
        const int buf = s & (NSTAGE - 1);
        const uint8_t* ap = Ag + s * 64;
        const uint8_t* bp = Bg + s * 64;
        const uint32_t da = dstA + buf * STAGE_T;
        const uint32_t db = dstB + buf * STAGE_T;
#pragma unroll
        for (int i = 0; i < 2; i++) {
            CP_ASYNC16(da + i * 64 * RPAD_B, ap + (long long)(64 * i) * lda);
            CP_ASYNC16(db + i * 64 * RPAD_B, bp + (long long)(64 * i) * ldb);
        }
    };
    auto compute_stage = [&](int buf) {
        const uint32_t ab = a_off + buf * STAGE_T;
        const uint32_t bb = b_off + buf * STAGE_T;
#pragma unroll
        for (int kb = 0; kb < 2; kb++) {          // two 32B chunks = two k32 steps
            uint32_t afr[4][4], bfr[2][4];
#pragma unroll
            for (int mt = 0; mt < 4; mt++)
                LDSM_X4(afr[mt][0], afr[mt][1], afr[mt][2], afr[mt][3],
                        ab + mt * (16 * RPAD_B) + kb * 32);
#pragma unroll
            for (int t = 0; t < 2; t++)
                LDSM_X4(bfr[t][0], bfr[t][1], bfr[t][2], bfr[t][3],
                        bb + t * (16 * RPAD_B) + kb * 32);
#pragma unroll
            for (int mt = 0; mt < 4; mt++)
#pragma unroll
                for (int nt = 0; nt < 4; nt++)
                    mma_fp8(acc[mt][nt], afr[mt],
                            bfr[nt >> 1][nt & 1], bfr[nt >> 1][2 + (nt & 1)]);
        }
    };

    const int nst = K >> 6;                       // 64 elements per stage
#pragma unroll
    for (int s = 0; s < NSTAGE - 1; s++) { issue_stage(s); CP_COMMIT(); }
    for (int s = 0; s < nst; s++) {
        CP_WAIT(NSTAGE - 2);
        __syncthreads();
        if (s + NSTAGE - 1 < nst) issue_stage(s + NSTAGE - 1);
        CP_COMMIT();
        compute_stage(s & (NSTAGE - 1));
    }

    const int lr  = l >> 2;
    const int lc2 = (l & 3) * 2;
#pragma unroll
    for (int mt = 0; mt < 4; mt++) {
        const int rA = wm * 64 + mt * 16 + lr;
#pragma unroll
        for (int nt = 0; nt < 4; nt++) {
            const int cA = wn * 32 + nt * 8 + lc2;
            float2 v0, v1;
            v0.x = acc[mt][nt][0] * alpha; v0.y = acc[mt][nt][1] * alpha;
            v1.x = acc[mt][nt][2] * alpha; v1.y = acc[mt][nt][3] * alpha;
            *(__nv_bfloat162*)(C + cbase + (long long)rA * ldc + cA) =
                __float22bfloat162_rn(v0);
            *(__nv_bfloat162*)(C + cbase + (long long)(rA + 8) * ldc + cA) =
                __float22bfloat162_rn(v1);
        }
    }
}

// ---------------- X -> bf16 ----------------
__global__ __launch_bounds__(256) void cvt_x_k(const float* __restrict__ X,
                                               __nv_bfloat16* __restrict__ Xb)
{
    const size_t i = ((size_t)blockIdx.x * 256 + threadIdx.x) * 4;
    float4 v = *(const float4*)(X + i);
    *(__nv_bfloat162*)(Xb + i)     = __float22bfloat162_rn(make_float2(v.x, v.y));
    *(__nv_bfloat162*)(Xb + i + 2) = __float22bfloat162_rn(make_float2(v.z, v.w));
}

// ---------------- weight transpose -> bf16: WT[n,k] = W[k,n] ----------------
__global__ __launch_bounds__(256) void transpose4_k(
    const float* __restrict__ w0, const float* __restrict__ w1,
    const float* __restrict__ w2, const float* __restrict__ w3,
    __nv_bfloat16* __restrict__ out)
{
    __shared__ float t[32][33];
    const int z = blockIdx.z;
    const float* W = (z == 0) ? w0 : (z == 1) ? w1 : (z == 2) ? w2 : w3;
    __nv_bfloat16* O = out + (size_t)z * Dq * Hq;
    const int tx = threadIdx.x & 31;
    const int ty = threadIdx.x >> 5;
    const int x = blockIdx.x * 32 + tx;
    const int y0 = blockIdx.y * 32;
#pragma unroll
    for (int i = ty; i < 32; i += 8) t[i][tx] = W[(y0 + i) * Hq + x];
    __syncthreads();
    const int ox = blockIdx.y * 32 + tx;
#pragma unroll
    for (int i = ty; i < 32; i += 8)
        O[(blockIdx.x * 32 + i) * Dq + ox] = __float2bfloat16_rn(t[tx][i]);
}

// ---------------- softmax: bf16 scores -> fp8 probs (x256) ----------------
__global__ __launch_bounds__(256) void softmax_k(const __nv_bfloat16* __restrict__ S,
                                                 uint8_t* __restrict__ P)
{
    __shared__ float red[256];
    const __nv_bfloat16* p = S + blockIdx.x * (long long)Nq;
    uint8_t* po = P + blockIdx.x * (long long)Nq;
    const int t = threadIdx.x;

    uint4 raw = *(const uint4*)(p + t * 8);
    const __nv_bfloat162* h2 = (const __nv_bfloat162*)&raw;
    float v[8];
#pragma unroll
    for (int i = 0; i < 4; i++) {
        float2 f = __bfloat1622float2(h2[i]);
        v[2 * i] = f.x; v[2 * i + 1] = f.y;
    }
    float mx = v[0];
#pragma unroll
    for (int i = 1; i < 8; i++) mx = fmaxf(mx, v[i]);
    red[t] = mx; __syncthreads();
    for (int s = 128; s > 0; s >>= 1) { if (t < s) red[t] = fmaxf(red[t], red[t + s]); __syncthreads(); }
    const float m = red[0]; __syncthreads();
    float sum = 0.f;
#pragma unroll
    for (int i = 0; i < 8; i++) { v[i] = __expf(v[i] - m); sum += v[i]; }
    red[t] = sum; __syncthreads();
    for (int s = 128; s > 0; s >>= 1) { if (t < s) red[t] += red[t + s]; __syncthreads(); }
    const float inv = 256.f / red[0];             // scale x256 into fp8 normal range
    uint16_t w[4];
#pragma unroll
    for (int i = 0; i < 4; i++)
        w[i] = f2_to_fp8x2(v[2 * i] * inv, v[2 * i + 1] * inv);
    uint2 packed;
    packed.x = (uint32_t)w[0] | ((uint32_t)w[1] << 16);
    packed.y = (uint32_t)w[2] | ((uint32_t)w[3] << 16);
    *(uint2*)(po + t * 8) = packed;
}

// ---------------- LayerNorm over last dim (512) ----------------
__global__ __launch_bounds__(256) void ln_k(
    const float* __restrict__ in, const float* __restrict__ gamma,
    const float* __restrict__ beta, float* __restrict__ out)
{
    __shared__ float red[256];
    const float* p = in + blockIdx.x * (long long)Dq;
    const int t = threadIdx.x;
    float a = p[t], b = p[t + 256];
    red[t] = a + b; __syncthreads();
    for (int s = 128; s > 0; s >>= 1) { if (t < s) red[t] += red[t + s]; __syncthreads(); }
    const float mu = red[0] * (1.f / Dq); __syncthreads();
    float da = a - mu, db = b - mu;
    red[t] = da * da + db * db; __syncthreads();
    for (int s = 128; s > 0; s >>= 1) { if (t < s) red[t] += red[t + s]; __syncthreads(); }
    const float inv = rsqrtf(red[0] * (1.f / Dq) + 1e-5f);
    out[blockIdx.x * (long long)Dq + t]       = da * inv * gamma[t]       + beta[t];
    out[blockIdx.x * (long long)Dq + t + 256] = db * inv * gamma[t + 256] + beta[t + 256];
}

// ---------------- launch ----------------
extern "C" void kernel_launch(void* const* d_in, const int* in_sizes, int n_in,
                              void* d_out, int out_size)
{
    const float* X   = (const float*)d_in[0];
    const float* Wq  = (const float*)d_in[1];
    const float* bqp = (const float*)d_in[2];
    const float* Wk  = (const float*)d_in[3];
    const float* bkp = (const float*)d_in[4];
    const float* Wv  = (const float*)d_in[5];
    const float* bvp = (const float*)d_in[6];
    const float* Wo  = (const float*)d_in[7];
    const float* bop = (const float*)d_in[8];
    const float* ga  = (const float*)d_in[9];
    const float* be  = (const float*)d_in[10];
    float* out = (float*)d_out;

    void *pxb, *pq8, *pk8, *pv8T, *pp8, *pattnb, *pctxb, *pwtb, *ptmp;
    cudaGetSymbolAddress(&pxb, g_xb);
    cudaGetSymbolAddress(&pq8, g_q8);
    cudaGetSymbolAddress(&pk8, g_k8);
    cudaGetSymbolAddress(&pv8T, g_v8T);
    cudaGetSymbolAddress(&pp8, g_p8);
    cudaGetSymbolAddress(&pattnb, g_attnb);
    cudaGetSymbolAddress(&pctxb, g_ctxb);
    cudaGetSymbolAddress(&pwtb, g_wtb);
    cudaGetSymbolAddress(&ptmp, g_tmp);
    __nv_bfloat16* xb    = (__nv_bfloat16*)pxb;
    uint8_t* q8  = (uint8_t*)pq8;
    uint8_t* k8  = (uint8_t*)pk8;
    uint8_t* v8T = (uint8_t*)pv8T;
    uint8_t* p8  = (uint8_t*)pp8;
    __nv_bfloat16* attnb = (__nv_bfloat16*)pattnb;
    __nv_bfloat16* ctxb  = (__nv_bfloat16*)pctxb;
    __nv_bfloat16* wtb   = (__nv_bfloat16*)pwtb;
    float* tmp = (float*)ptmp;
    __nv_bfloat16* WqT = wtb;
    __nv_bfloat16* WkT = wtb + (size_t)Dq * Hq;
    __nv_bfloat16* WvT = wtb + (size_t)2 * Dq * Hq;
    __nv_bfloat16* WoT = wtb + (size_t)3 * Dq * Hq;

    cudaFuncSetAttribute(mma_gemm<1, false, 2>, cudaFuncAttributeMaxDynamicSharedMemorySize, SMEM_TOTAL);
    cudaFuncSetAttribute(mma_gemm<2, false, 2>, cudaFuncAttributeMaxDynamicSharedMemorySize, SMEM_TOTAL);
    cudaFuncSetAttribute(mma_gemm<1, true, 0>,  cudaFuncAttributeMaxDynamicSharedMemorySize, SMEM_TOTAL);
    cudaFuncSetAttribute(mma_gemm_f8, cudaFuncAttributeMaxDynamicSharedMemorySize, SMEM_TOTAL);

    const float inv_sqrt_h = 0.04419417382415922f;  // 1/sqrt(512)
    dim3 blk(256);

    // 0. convert X; transpose+convert weights
    cvt_x_k<<<(ROWS * Dq) / (256 * 4), blk>>>(X, xb);
    transpose4_k<<<dim3(16, 16, 4), blk>>>(Wq, Wk, Wv, Wo, wtb);

    // 1. q8 = fp8(X @ Wq + bq)
    mma_gemm<1, false, 2><<<dim3(Hq / 128, ROWS / 128, 1), blk, SMEM_TOTAL>>>(
        xb, WqT, bqp, nullptr, q8, Dq, Dq, Dq, Hq, 0, 0, 0, 1.f);
    // 2. k8 = fp8(X @ Wk + bk)
    mma_gemm<1, false, 2><<<dim3(Hq / 128, ROWS / 128, 1), blk, SMEM_TOTAL>>>(
        xb, WkT, bkp, nullptr, k8, Dq, Dq, Dq, Hq, 0, 0, 0, 1.f);
    // 3. v8T[h,n] = fp8(Wv[:,h].X[n,:] + bv[h])  (row bias)
    mma_gemm<2, false, 2><<<dim3(ROWS / 128, Hq / 128, 1), blk, SMEM_TOTAL>>>(
        WvT, xb, bvp, nullptr, v8T, Dq, Dq, Dq, ROWS, 0, 0, 0, 1.f);
    // 4. scores = q8 @ k8^T / sqrt(H)  (fp8 GEMM -> bf16, batched)
    mma_gemm_f8<<<dim3(Nq / 128, Nq / 128, Bq), blk, SMEM_TOTAL>>>(
        q8, k8, attnb, Hq, Hq, Hq, Nq,
        (long long)Nq * Hq, (long long)Nq * Hq, (long long)Nq * Nq, inv_sqrt_h);
    // 5. softmax (bf16 -> fp8 probs x256)
    softmax_k<<<ROWS, blk>>>(attnb, p8);
    // 6. ctx = (probs/256) @ v  (fp8 GEMM -> bf16)
    mma_gemm_f8<<<dim3(Hq / 128, Nq / 128, Bq), blk, SMEM_TOTAL>>>(
        p8, v8T, ctxb, Nq, Nq, ROWS, Hq,
        (long long)Nq * Nq, (long long)Nq, (long long)Nq * Hq, 1.f / 256.f);
    // 7. out_pre = ctx @ Wo + bo + X  (bf16 GEMM -> fp32)
    mma_gemm<1, true, 0><<<dim3(Dq / 128, ROWS / 128, 1), blk, SMEM_TOTAL>>>(
        ctxb, WoT, bop, X, tmp, Hq, Hq, Hq, Dq, 0, 0, 0, 1.f);
    // 8. LayerNorm
    ln_k<<<ROWS, blk>>>(tmp, ga, be, out);
}

// round 8
// speedup vs baseline: 1.0673x; 1.0238x over previous
#include <cuda_runtime.h>
#include <cuda_bf16.h>
#include <cuda_fp8.h>
#include <cstdint>
#include <math_constants.h>

// ---------------- problem constants ----------------
#define Bq 8
#define Nq 2048
#define Dq 512
#define Hq 512
#define ROWS (Bq * Nq)          // 16384

// ---------------- scratch (device globals) ----------------
__device__ __nv_bfloat16 g_xb[(size_t)ROWS * Dq];
__device__ uint8_t g_q8[(size_t)ROWS * Hq];
__device__ uint8_t g_k8[(size_t)ROWS * Hq];
__device__ uint8_t g_v8T[(size_t)Hq * ROWS];             // v fp8, transposed [H, B*N]
__device__ uint8_t g_e8[(size_t)Bq * Nq * Nq];           // exp(scores)*8 in fp8
__device__ float g_rs[(size_t)ROWS];                     // row sums of exp*8
__device__ __nv_bfloat16 g_ctxb[(size_t)ROWS * Hq];
__device__ __nv_bfloat16 g_wtb[(size_t)4 * Dq * Hq];     // WqT, WkT, WvT, WoT
__device__ float g_tmp[(size_t)ROWS * Dq];               // pre-LN (fp32)

// ---------------- helpers ----------------
__device__ __forceinline__ uint32_t smem_u32(const void* p) {
    uint32_t a;
    asm("{ .reg .u64 t; cvta.to.shared.u64 t, %1; cvt.u32.u64 %0, t; }" : "=r"(a) : "l"(p));
    return a;
}
#define LDSM_X4(r0, r1, r2, r3, addr) \
    asm volatile("ldmatrix.sync.aligned.m8n8.x4.shared.b16 {%0,%1,%2,%3}, [%4];" \
        : "=r"(r0), "=r"(r1), "=r"(r2), "=r"(r3) : "r"(addr))
#define CP_ASYNC16(dst, src) \
    asm volatile("cp.async.cg.shared.global [%0], [%1], 16;" :: "r"(dst), "l"(src))
#define CP_COMMIT() asm volatile("cp.async.commit_group;" ::: "memory")
#define CP_WAIT(n)  asm volatile("cp.async.wait_group %0;" :: "n"(n) : "memory")

__device__ __forceinline__ void mma_bf16(float* d, const uint32_t* a,
                                         uint32_t b0, uint32_t b1) {
    asm volatile(
        "mma.sync.aligned.m16n8k16.row.col.f32.bf16.bf16.f32 "
        "{%0,%1,%2,%3}, {%4,%5,%6,%7}, {%8,%9}, {%0,%1,%2,%3};"
        : "+f"(d[0]), "+f"(d[1]), "+f"(d[2]), "+f"(d[3])
        : "r"(a[0]), "r"(a[1]), "r"(a[2]), "r"(a[3]), "r"(b0), "r"(b1));
}
__device__ __forceinline__ void mma_fp8(float* d, const uint32_t* a,
                                        uint32_t b0, uint32_t b1) {
    asm volatile(
        "mma.sync.aligned.m16n8k32.row.col.f32.e4m3.e4m3.f32 "
        "{%0,%1,%2,%3}, {%4,%5,%6,%7}, {%8,%9}, {%0,%1,%2,%3};"
        : "+f"(d[0]), "+f"(d[1]), "+f"(d[2]), "+f"(d[3])
        : "r"(a[0]), "r"(a[1]), "r"(a[2]), "r"(a[3]), "r"(b0), "r"(b1));
}
__device__ __forceinline__ uint16_t f2_to_fp8x2(float x, float y) {
    return (uint16_t)__nv_cvt_float2_to_fp8x2(make_float2(x, y),
                                              __NV_SATFINITE, __NV_E4M3);
}

// ---------------- shared tiling constants ----------------
// CTA tile 128x128; 256 threads; 8 warps (2 M x 4 N), warp 64x32.
// SMEM rows: 64 bytes payload padded to 80 B -> conflict-free ldmatrix.
// bf16: 64B row = 32 elements (k-stage 32). fp8: 64B row = 64 elements (k-stage 64).
#define RPAD_B 80
#define HALF_B (128 * RPAD_B)                     // 10240 per operand per stage
#define STAGE_T (2 * HALF_B)                      // 20480 (A + B)
#define NSTAGE 4
#define SMEM_TOTAL (NSTAGE * STAGE_T)             // 81920 (dynamic)

// ===================== bf16 GEMM =====================
// C[M,N] = alpha * A[M,K] @ B[N,K]^T (+ bias) (+ res). A,B bf16 K-major.
// BIASMODE: 0 none, 1 bias[col], 2 bias[row]. OUTMODE: 0 f32, 1 bf16, 2 fp8.
template<int BIASMODE, bool RES, int OUTMODE>
__global__ __launch_bounds__(256) void mma_gemm(
    const __nv_bfloat16* __restrict__ A, const __nv_bfloat16* __restrict__ B,
    const float* __restrict__ bias, const float* __restrict__ resid,
    void* __restrict__ Cv,
    int K, int lda, int ldb, int ldc,
    long long sA, long long sB, long long sC, float alpha)
{
    extern __shared__ char smem[];
    const uint32_t sb = smem_u32(smem);
    const int tid = threadIdx.x;
    const int wid = tid >> 5;
    const int l   = tid & 31;
    const int wm  = wid & 1;
    const int wn  = wid >> 1;
    const int bz  = blockIdx.z;
    const int row0 = blockIdx.y * 128;
    const int col0 = blockIdx.x * 128;

    A += (long long)bz * sA + (long long)row0 * lda;
    B += (long long)bz * sB + (long long)col0 * ldb;
    const long long cbase = (long long)bz * sC + (long long)row0 * ldc + col0;
    const float* Rp = RES ? (resid + cbase) : nullptr;

    const int r0  = tid >> 2;
    const int c16 = tid & 3;
    const __nv_bfloat16* Ag = A + (long long)r0 * lda + c16 * 8;
    const __nv_bfloat16* Bg = B + (long long)r0 * ldb + c16 * 8;
    const uint32_t dstA = sb + (uint32_t)(r0 * RPAD_B + c16 * 16);
    const uint32_t dstB = dstA + HALF_B;

    const uint32_t a_off = sb
        + (uint32_t)((wm * 64 + (l & 15)) * RPAD_B + ((l >> 4) & 1) * 16);
    const uint32_t b_off = sb + HALF_B
        + (uint32_t)((wn * 32 + (l & 15)) * RPAD_B + ((l >> 4) & 1) * 16);

    float acc[4][4][4];
#pragma unroll
    for (int mt = 0; mt < 4; mt++)
#pragma unroll
        for (int nt = 0; nt < 4; nt++)
#pragma unroll
            for (int i = 0; i < 4; i++) acc[mt][nt][i] = 0.f;

    auto issue_stage = [&](int s) {
        const int buf = s & (NSTAGE - 1);
        const __nv_bfloat16* ap = Ag + s * 32;
        const __nv_bfloat16* bp = Bg + s * 32;
        const uint32_t da = dstA + buf * STAGE_T;
        const uint32_t db = dstB + buf * STAGE_T;
#pragma unroll
        for (int i = 0; i < 2; i++) {
            CP_ASYNC16(da + i * 64 * RPAD_B, ap + (long long)(64 * i) * lda);
            CP_ASYNC16(db + i * 64 * RPAD_B, bp + (long long)(64 * i) * ldb);
        }
    };
    auto compute_stage = [&](int buf) {
        const uint32_t ab = a_off + buf * STAGE_T;
        const uint32_t bb = b_off + buf * STAGE_T;
#pragma unroll
        for (int kb = 0; kb < 2; kb++) {
            uint32_t afr[4][4], bfr[2][4];
#pragma unroll
            for (int mt = 0; mt < 4; mt++)
                LDSM_X4(afr[mt][0], afr[mt][1], afr[mt][2], afr[mt][3],
                        ab + mt * (16 * RPAD_B) + kb * 32);
#pragma unroll
            for (int t = 0; t < 2; t++)
                LDSM_X4(bfr[t][0], bfr[t][1], bfr[t][2], bfr[t][3],
                        bb + t * (16 * RPAD_B) + kb * 32);
#pragma unroll
            for (int mt = 0; mt < 4; mt++)
#pragma unroll
                for (int nt = 0; nt < 4; nt++)
                    mma_bf16(acc[mt][nt], afr[mt],
                             bfr[nt >> 1][nt & 1], bfr[nt >> 1][2 + (nt & 1)]);
        }
    };

    const int nst = K >> 5;
#pragma unroll
    for (int s = 0; s < NSTAGE - 1; s++) { issue_stage(s); CP_COMMIT(); }
    for (int s = 0; s < nst; s++) {
        CP_WAIT(NSTAGE - 2);
        __syncthreads();
        if (s + NSTAGE - 1 < nst) issue_stage(s + NSTAGE - 1);
        CP_COMMIT();
        compute_stage(s & (NSTAGE - 1));
    }

    // ---- epilogue
    float* Cf = (float*)Cv;
    __nv_bfloat16* Cb = (__nv_bfloat16*)Cv;
    uint8_t* C8 = (uint8_t*)Cv;
    const int lr  = l >> 2;
    const int lc2 = (l & 3) * 2;
#pragma unroll
    for (int mt = 0; mt < 4; mt++) {
        const int rA = wm * 64 + mt * 16 + lr;
        float blo = 0.f, bhi = 0.f;
        if (BIASMODE == 2) { blo = bias[row0 + rA]; bhi = bias[row0 + rA + 8]; }
#pragma unroll
        for (int nt = 0; nt < 4; nt++) {
            const int cA = wn * 32 + nt * 8 + lc2;
            float2 v0, v1;
            v0.x = acc[mt][nt][0] * alpha; v0.y = acc[mt][nt][1] * alpha;
            v1.x = acc[mt][nt][2] * alpha; v1.y = acc[mt][nt][3] * alpha;
            if (BIASMODE == 1) {
                float2 bb2 = *(const float2*)(bias + col0 + cA);
                v0.x += bb2.x; v0.y += bb2.y; v1.x += bb2.x; v1.y += bb2.y;
            } else if (BIASMODE == 2) {
                v0.x += blo; v0.y += blo; v1.x += bhi; v1.y += bhi;
            }
            if (RES) {
                float2 q0 = *(const float2*)(Rp + (long long)rA * ldc + cA);
                float2 q1 = *(const float2*)(Rp + (long long)(rA + 8) * ldc + cA);
                v0.x += q0.x; v0.y += q0.y; v1.x += q1.x; v1.y += q1.y;
            }
            if (OUTMODE == 1) {
                *(__nv_bfloat162*)(Cb + cbase + (long long)rA * ldc + cA) =
                    __float22bfloat162_rn(v0);
                *(__nv_bfloat162*)(Cb + cbase + (long long)(rA + 8) * ldc + cA) =
                    __float22bfloat162_rn(v1);
            } else if (OUTMODE == 2) {
                *(uint16_t*)(C8 + cbase + (long long)rA * ldc + cA) =
                    f2_to_fp8x2(v0.x, v0.y);
                *(uint16_t*)(C8 + cbase + (long long)(rA + 8) * ldc + cA) =
                    f2_to_fp8x2(v1.x, v1.y);
            } else {
                *(float2*)(Cf + cbase + (long long)rA * ldc + cA) = v0;
                *(float2*)(Cf + cbase + (long long)(rA + 8) * ldc + cA) = v1;
            }
        }
    }
}

// ===================== fp8 GEMM =====================
// MODE 0 (scores): C = fp8( 8*exp(alpha * A@B^T) ); atomicAdd row sums into rs.
// MODE 1 (ctx):    C = bf16( (A@B^T) / rs[row] )
template<int MODE>
__global__ __launch_bounds__(256) void mma_gemm_f8(
    const uint8_t* __restrict__ A, const uint8_t* __restrict__ B,
    void* __restrict__ Cv, float* __restrict__ rs,
    int K, int lda, int ldb, int ldc,
    long long sA, long long sB, long long sC, float alpha)
{
    extern __shared__ char smem[];
    const uint32_t sb = smem_u32(smem);
    const int tid = threadIdx.x;
    const int wid = tid >> 5;
    const int l   = tid & 31;
    const int wm  = wid & 1;
    const int wn  = wid >> 1;
    const int bz  = blockIdx.z;
    const int row0 = blockIdx.y * 128;
    const int col0 = blockIdx.x * 128;

    A += (long long)bz * sA + (long long)row0 * lda;
    B += (long long)bz * sB + (long long)col0 * ldb;
    const long long cbase = (long long)bz * sC + (long long)row0 * ldc + col0;
    float* rsp = rs + (long long)bz * Nq + row0;   // row sums for this tile's rows

    const int r0  = tid >> 2;
    const int c16 = tid & 3;
    const uint8_t* Ag = A + (long long)r0 * lda + c16 * 16;
    const uint8_t* Bg = B + (long long)r0 * ldb + c16 * 16;
    const uint32_t dstA = sb + (uint32_t)(r0 * RPAD_B + c16 * 16);
    const uint32_t dstB = dstA + HALF_B;

    const uint32_t a_off = sb
        + (uint32_t)((wm * 64 + (l & 15)) * RPAD_B + ((l >> 4) & 1) * 16);
    const uint32_t b_off = sb + HALF_B
        + (uint32_t)((wn * 32 + (l & 15)) * RPAD_B + ((l >> 4) & 1) * 16);

    float acc[4][4][4];
#pragma unroll
    for (int mt = 0; mt < 4; mt++)
#pragma unroll
        for (int nt = 0; nt < 4; nt++)
#pragma unroll
            for (int i = 0; i < 4; i++) acc[mt][nt][i] = 0.f;

    auto issue_stage = [&](int s) {
        const int buf = s & (NSTAGE - 1);
        const uint8_t* ap = Ag + s * 64;
        const uint8_t* bp = Bg + s * 64;
        const uint32_t da = dstA + buf * STAGE_T;
        const uint32_t db = dstB + buf * STAGE_T;
#pragma unroll
        for (int i = 0; i < 2; i++) {
            CP_ASYNC16(da + i * 64 * RPAD_B, ap + (long long)(64 * i) * lda);
            CP_ASYNC16(db + i * 64 * RPAD_B, bp + (long long)(64 * i) * ldb);
        }
    };
    auto compute_stage = [&](int buf) {
        const uint32_t ab = a_off + buf * STAGE_T;
        const uint32_t bb = b_off + buf * STAGE_T;
#pragma unroll
        for (int kb = 0; kb < 2; kb++) {
            uint32_t afr[4][4], bfr[2][4];
#pragma unroll
            for (int mt = 0; mt < 4; mt++)
                LDSM_X4(afr[mt][0], afr[mt][1], afr[mt][2], afr[mt][3],
                        ab + mt * (16 * RPAD_B) + kb * 32);
#pragma unroll
            for (int t = 0; t < 2; t++)
                LDSM_X4(bfr[t][0], bfr[t][1], bfr[t][2], bfr[t][3],
                        bb + t * (16 * RPAD_B) + kb * 32);
#pragma unroll
            for (int mt = 0; mt < 4; mt++)
#pragma unroll
                for (int nt = 0; nt < 4; nt++)
                    mma_fp8(acc[mt][nt], afr[mt],
                            bfr[nt >> 1][nt & 1], bfr[nt >> 1][2 + (nt & 1)]);
        }
    };

    const int nst = K >> 6;                       // 64 elements per stage
#pragma unroll
    for (int s = 0; s < NSTAGE - 1; s++) { issue_stage(s); CP_COMMIT(); }
    for (int s = 0; s < nst; s++) {
        CP_WAIT(NSTAGE - 2);
        __syncthreads();
        if (s + NSTAGE - 1 < nst) issue_stage(s + NSTAGE - 1);
        CP_COMMIT();
        compute_stage(s & (NSTAGE - 1));
    }

    uint8_t* C8 = (uint8_t*)Cv;
    __nv_bfloat16* Cb = (__nv_bfloat16*)Cv;
    const int lr  = l >> 2;
    const int lc2 = (l & 3) * 2;
#pragma unroll
    for (int mt = 0; mt < 4; mt++) {
        const int rA = wm * 64 + mt * 16 + lr;
        float sl = 0.f, sh = 0.f;
        float invl = 1.f, invh = 1.f;
        if (MODE == 1) { invl = 1.f / rsp[rA]; invh = 1.f / rsp[rA + 8]; }
#pragma unroll
        for (int nt = 0; nt < 4; nt++) {
            const int cA = wn * 32 + nt * 8 + lc2;
            float2 v0, v1;
            v0.x = acc[mt][nt][0] * alpha; v0.y = acc[mt][nt][1] * alpha;
            v1.x = acc[mt][nt][2] * alpha; v1.y = acc[mt][nt][3] * alpha;
            if (MODE == 0) {
                // exp (max-free; scores are O(1)) scaled x8 into fp8 normal range
                v0.x = __expf(v0.x) * 8.f; v0.y = __expf(v0.y) * 8.f;
                v1.x = __expf(v1.x) * 8.f; v1.y = __expf(v1.y) * 8.f;
                sl += v0.x + v0.y;
                sh += v1.x + v1.y;
                *(uint16_t*)(C8 + cbase + (long long)rA * ldc + cA) =
                    f2_to_fp8x2(v0.x, v0.y);
                *(uint16_t*)(C8 + cbase + (long long)(rA + 8) * ldc + cA) =
                    f2_to_fp8x2(v1.x, v1.y);
            } else {
                v0.x *= invl; v0.y *= invl;
                v1.x *= invh; v1.y *= invh;
                *(__nv_bfloat162*)(Cb + cbase + (long long)rA * ldc + cA) =
                    __float22bfloat162_rn(v0);
                *(__nv_bfloat162*)(Cb + cbase + (long long)(rA + 8) * ldc + cA) =
                    __float22bfloat162_rn(v1);
            }
        }
        if (MODE == 0) {
            // quad-reduce (lanes l&3 share a row), then one atomic per row chunk
            sl += __shfl_xor_sync(0xFFFFFFFF, sl, 1);
            sl += __shfl_xor_sync(0xFFFFFFFF, sl, 2);
            sh += __shfl_xor_sync(0xFFFFFFFF, sh, 1);
            sh += __shfl_xor_sync(0xFFFFFFFF, sh, 2);
            if ((l & 3) == 0) {
                atomicAdd(&rsp[rA], sl);
                atomicAdd(&rsp[rA + 8], sh);
            }
        }
    }
}

// ---------------- X -> bf16 ----------------
__global__ __launch_bounds__(256) void cvt_x_k(const float* __restrict__ X,
                                               __nv_bfloat16* __restrict__ Xb)
{
    const size_t i = ((size_t)blockIdx.x * 256 + threadIdx.x) * 4;
    float4 v = *(const float4*)(X + i);
    *(__nv_bfloat162*)(Xb + i)     = __float22bfloat162_rn(make_float2(v.x, v.y));
    *(__nv_bfloat162*)(Xb + i + 2) = __float22bfloat162_rn(make_float2(v.z, v.w));
}

// ---------------- weight transpose -> bf16: WT[n,k] = W[k,n] ----------------
__global__ __launch_bounds__(256) void transpose4_k(
    const float* __restrict__ w0, const float* __restrict__ w1,
    const float* __restrict__ w2, const float* __restrict__ w3,
    __nv_bfloat16* __restrict__ out)
{
    __shared__ float t[32][33];
    const int z = blockIdx.z;
    const float* W = (z == 0) ? w0 : (z == 1) ? w1 : (z == 2) ? w2 : w3;
    __nv_bfloat16* O = out + (size_t)z * Dq * Hq;
    const int tx = threadIdx.x & 31;
    const int ty = threadIdx.x >> 5;
    const int x = blockIdx.x * 32 + tx;
    const int y0 = blockIdx.y * 32;
#pragma unroll
    for (int i = ty; i < 32; i += 8) t[i][tx] = W[(y0 + i) * Hq + x];
    __syncthreads();
    const int ox = blockIdx.y * 32 + tx;
#pragma unroll
    for (int i = ty; i < 32; i += 8)
        O[(blockIdx.x * 32 + i) * Dq + ox] = __float2bfloat16_rn(t[tx][i]);
}

// ---------------- LayerNorm over last dim (512) ----------------
__global__ __launch_bounds__(256) void ln_k(
    const float* __restrict__ in, const float* __restrict__ gamma,
    const float* __restrict__ beta, float* __restrict__ out)
{
    __shared__ float red[256];
    const float* p = in + blockIdx.x * (long long)Dq;
    const int t = threadIdx.x;
    float a = p[t], b = p[t + 256];
    red[t] = a + b; __syncthreads();
    for (int s = 128; s > 0; s >>= 1) { if (t < s) red[t] += red[t + s]; __syncthreads(); }
    const float mu = red[0] * (1.f / Dq); __syncthreads();
    float da = a - mu, db = b - mu;
    red[t] = da * da + db * db; __syncthreads();
    for (int s = 128; s > 0; s >>= 1) { if (t < s) red[t] += red[t + s]; __syncthreads(); }
    const float inv = rsqrtf(red[0] * (1.f / Dq) + 1e-5f);
    out[blockIdx.x * (long long)Dq + t]       = da * inv * gamma[t]       + beta[t];
    out[blockIdx.x * (long long)Dq + t + 256] = db * inv * gamma[t + 256] + beta[t + 256];
}

// ---------------- launch ----------------
extern "C" void kernel_launch(void* const* d_in, const int* in_sizes, int n_in,
                              void* d_out, int out_size)
{
    const float* X   = (const float*)d_in[0];
    const float* Wq  = (const float*)d_in[1];
    const float* bqp = (const float*)d_in[2];
    const float* Wk  = (const float*)d_in[3];
    const float* bkp = (const float*)d_in[4];
    const float* Wv  = (const float*)d_in[5];
    const float* bvp = (const float*)d_in[6];
    const float* Wo  = (const float*)d_in[7];
    const float* bop = (const float*)d_in[8];
    const float* ga  = (const float*)d_in[9];
    const float* be  = (const float*)d_in[10];
    float* out = (float*)d_out;

    void *pxb, *pq8, *pk8, *pv8T, *pe8, *prs, *pctxb, *pwtb, *ptmp;
    cudaGetSymbolAddress(&pxb, g_xb);
    cudaGetSymbolAddress(&pq8, g_q8);
    cudaGetSymbolAddress(&pk8, g_k8);
    cudaGetSymbolAddress(&pv8T, g_v8T);
    cudaGetSymbolAddress(&pe8, g_e8);
    cudaGetSymbolAddress(&prs, g_rs);
    cudaGetSymbolAddress(&pctxb, g_ctxb);
    cudaGetSymbolAddress(&pwtb, g_wtb);
    cudaGetSymbolAddress(&ptmp, g_tmp);
    __nv_bfloat16* xb    = (__nv_bfloat16*)pxb;
    uint8_t* q8  = (uint8_t*)pq8;
    uint8_t* k8  = (uint8_t*)pk8;
    uint8_t* v8T = (uint8_t*)pv8T;
    uint8_t* e8  = (uint8_t*)pe8;
    float*   rs  = (float*)prs;
    __nv_bfloat16* ctxb  = (__nv_bfloat16*)pctxb;
    __nv_bfloat16* wtb   = (__nv_bfloat16*)pwtb;
    float* tmp = (float*)ptmp;
    __nv_bfloat16* WqT = wtb;
    __nv_bfloat16* WkT = wtb + (size_t)Dq * Hq;
    __nv_bfloat16* WvT = wtb + (size_t)2 * Dq * Hq;
    __nv_bfloat16* WoT = wtb + (size_t)3 * Dq * Hq;

    cudaFuncSetAttribute(mma_gemm<1, false, 2>, cudaFuncAttributeMaxDynamicSharedMemorySize, SMEM_TOTAL);
    cudaFuncSetAttribute(mma_gemm<2, false, 2>, cudaFuncAttributeMaxDynamicSharedMemorySize, SMEM_TOTAL);
    cudaFuncSetAttribute(mma_gemm<1, true, 0>,  cudaFuncAttributeMaxDynamicSharedMemorySize, SMEM_TOTAL);
    cudaFuncSetAttribute(mma_gemm_f8<0>, cudaFuncAttributeMaxDynamicSharedMemorySize, SMEM_TOTAL);
    cudaFuncSetAttribute(mma_gemm_f8<1>, cudaFuncAttributeMaxDynamicSharedMemorySize, SMEM_TOTAL);

    const float inv_sqrt_h = 0.04419417382415922f;  // 1/sqrt(512)
    dim3 blk(256);

    // 0. zero row sums; convert X; transpose+convert weights
    cudaMemsetAsync(rs, 0, (size_t)ROWS * sizeof(float));
    cvt_x_k<<<(ROWS * Dq) / (256 * 4), blk>>>(X, xb);
    transpose4_k<<<dim3(16, 16, 4), blk>>>(Wq, Wk, Wv, Wo, wtb);

    // 1. q8 = fp8(X @ Wq + bq)
    mma_gemm<1, false, 2><<<dim3(Hq / 128, ROWS / 128, 1), blk, SMEM_TOTAL>>>(
        xb, WqT, bqp, nullptr, q8, Dq, Dq, Dq, Hq, 0, 0, 0, 1.f);
    // 2. k8 = fp8(X @ Wk + bk)
    mma_gemm<1, false, 2><<<dim3(Hq / 128, ROWS / 128, 1), blk, SMEM_TOTAL>>>(
        xb, WkT, bkp, nullptr, k8, Dq, Dq, Dq, Hq, 0, 0, 0, 1.f);
    // 3. v8T[h,n] = fp8(Wv[:,h].X[n,:] + bv[h])  (row bias)
    mma_gemm<2, false, 2><<<dim3(ROWS / 128, Hq / 128, 1), blk, SMEM_TOTAL>>>(
        WvT, xb, bvp, nullptr, v8T, Dq, Dq, Dq, ROWS, 0, 0, 0, 1.f);
    // 4. e8 = fp8(8*exp(q8 @ k8^T / sqrt(H))); rs += row sums  (fused softmax part 1)
    mma_gemm_f8<0><<<dim3(Nq / 128, Nq / 128, Bq), blk, SMEM_TOTAL>>>(
        q8, k8, e8, rs, Hq, Hq, Hq, Nq,
        (long long)Nq * Hq, (long long)Nq * Hq, (long long)Nq * Nq, inv_sqrt_h);
    // 5. ctx = (e8 @ v8T) / rs[row]  (fused softmax part 2)
    mma_gemm_f8<1><<<dim3(Hq / 128, Nq / 128, Bq), blk, SMEM_TOTAL>>>(
        e8, v8T, ctxb, rs, Nq, Nq, ROWS, Hq,
        (long long)Nq * Nq, (long long)Nq, (long long)Nq * Hq, 1.f);
    // 6. out_pre = ctx @ Wo + bo + X  (bf16 GEMM -> fp32)
    mma_gemm<1, true, 0><<<dim3(Dq / 128, ROWS / 128, 1), blk, SMEM_TOTAL>>>(
        ctxb, WoT, bop, X, tmp, Hq, Hq, Hq, Dq, 0, 0, 0, 1.f);
    // 7. LayerNorm
    ln_k<<<ROWS, blk>>>(tmp, ga, be, out);
}

// round 9
// speedup vs baseline: 1.1092x; 1.0393x over previous
#include <cuda_runtime.h>
#include <cuda_bf16.h>
#include <cuda_fp8.h>
#include <cstdint>
#include <math_constants.h>

// ---------------- problem constants ----------------
#define Bq 8
#define Nq 2048
#define Dq 512
#define Hq 512
#define ROWS (Bq * Nq)          // 16384

// ---------------- scratch (device globals) ----------------
__device__ uint8_t g_x8[(size_t)ROWS * Dq];              // X in fp8
__device__ uint8_t g_y8[(size_t)ROWS * Dq];              // y = X@W'' fp8
__device__ uint8_t g_u8T[(size_t)Dq * ROWS];             // u^T = (X@W')^T fp8
__device__ uint8_t g_e8[(size_t)Bq * Nq * Nq];           // exp(scores)*8 fp8
__device__ float g_rs[(size_t)ROWS];                     // row sums of 8*exp
__device__ __nv_bfloat16 g_wb[(size_t)4 * Dq * Hq];      // Wq_b, Wk_b, Wv_b, WoT_b
__device__ uint8_t g_wpp8[(size_t)Dq * Dq];              // (W''^T)*16 fp8
__device__ uint8_t g_wp8[(size_t)Dq * Dq];               // (W'^T)*16 fp8
__device__ float g_g1[Dq];                               // Wk @ bq
__device__ float g_c2s[(size_t)ROWS];                    // (X @ g1)/sqrt(H)
__device__ float g_bias2[Dq];                            // bo + bv@Wo
__device__ float g_tmp[(size_t)ROWS * Dq];               // pre-LN fp32

// ---------------- helpers ----------------
__device__ __forceinline__ uint32_t smem_u32(const void* p) {
    uint32_t a;
    asm("{ .reg .u64 t; cvta.to.shared.u64 t, %1; cvt.u32.u64 %0, t; }" : "=r"(a) : "l"(p));
    return a;
}
#define LDSM_X4(r0, r1, r2, r3, addr) \
    asm volatile("ldmatrix.sync.aligned.m8n8.x4.shared.b16 {%0,%1,%2,%3}, [%4];" \
        : "=r"(r0), "=r"(r1), "=r"(r2), "=r"(r3) : "r"(addr))
#define CP_ASYNC16(dst, src) \
    asm volatile("cp.async.cg.shared.global [%0], [%1], 16;" :: "r"(dst), "l"(src))
#define CP_COMMIT() asm volatile("cp.async.commit_group;" ::: "memory")
#define CP_WAIT(n)  asm volatile("cp.async.wait_group %0;" :: "n"(n) : "memory")

__device__ __forceinline__ void mma_bf16(float* d, const uint32_t* a,
                                         uint32_t b0, uint32_t b1) {
    asm volatile(
        "mma.sync.aligned.m16n8k16.row.col.f32.bf16.bf16.f32 "
        "{%0,%1,%2,%3}, {%4,%5,%6,%7}, {%8,%9}, {%0,%1,%2,%3};"
        : "+f"(d[0]), "+f"(d[1]), "+f"(d[2]), "+f"(d[3])
        : "r"(a[0]), "r"(a[1]), "r"(a[2]), "r"(a[3]), "r"(b0), "r"(b1));
}
__device__ __forceinline__ void mma_fp8(float* d, const uint32_t* a,
                                        uint32_t b0, uint32_t b1) {
    asm volatile(
        "mma.sync.aligned.m16n8k32.row.col.f32.e4m3.e4m3.f32 "
        "{%0,%1,%2,%3}, {%4,%5,%6,%7}, {%8,%9}, {%0,%1,%2,%3};"
        : "+f"(d[0]), "+f"(d[1]), "+f"(d[2]), "+f"(d[3])
        : "r"(a[0]), "r"(a[1]), "r"(a[2]), "r"(a[3]), "r"(b0), "r"(b1));
}
__device__ __forceinline__ uint16_t f2_to_fp8x2(float x, float y) {
    return (uint16_t)__nv_cvt_float2_to_fp8x2(make_float2(x, y),
                                              __NV_SATFINITE, __NV_E4M3);
}

// ---------------- shared tiling constants ----------------
#define RPAD_B 80
#define HALF_B (128 * RPAD_B)                     // 10240
#define STAGE_T (2 * HALF_B)                      // 20480
#define NSTAGE 4
#define SMEM_TOTAL (NSTAGE * STAGE_T)             // 81920 (dynamic)

// ===================== bf16 GEMM (for the two 512^3 weight products) =====================
// C[M,N] = alpha * A[M,K] @ B[N,K]^T, fp8 output.
__global__ __launch_bounds__(256) void mma_gemm_w(
    const __nv_bfloat16* __restrict__ A, const __nv_bfloat16* __restrict__ B,
    uint8_t* __restrict__ C, int K, int lda, int ldb, int ldc, float alpha)
{
    extern __shared__ char smem[];
    const uint32_t sb = smem_u32(smem);
    const int tid = threadIdx.x;
    const int wid = tid >> 5;
    const int l   = tid & 31;
    const int wm  = wid & 1;
    const int wn  = wid >> 1;
    const int row0 = blockIdx.y * 128;
    const int col0 = blockIdx.x * 128;

    A += (long long)row0 * lda;
    B += (long long)col0 * ldb;
    const long long cbase = (long long)row0 * ldc + col0;

    const int r0  = tid >> 2;
    const int c16 = tid & 3;
    const __nv_bfloat16* Ag = A + (long long)r0 * lda + c16 * 8;
    const __nv_bfloat16* Bg = B + (long long)r0 * ldb + c16 * 8;
    const uint32_t dstA = sb + (uint32_t)(r0 * RPAD_B + c16 * 16);
    const uint32_t dstB = dstA + HALF_B;

    const uint32_t a_off = sb
        + (uint32_t)((wm * 64 + (l & 15)) * RPAD_B + ((l >> 4) & 1) * 16);
    const uint32_t b_off = sb + HALF_B
        + (uint32_t)((wn * 32 + (l & 15)) * RPAD_B + ((l >> 4) & 1) * 16);

    float acc[4][4][4];
#pragma unroll
    for (int mt = 0; mt < 4; mt++)
#pragma unroll
        for (int nt = 0; nt < 4; nt++)
#pragma unroll
            for (int i = 0; i < 4; i++) acc[mt][nt][i] = 0.f;

    auto issue_stage = [&](int s) {
        const int buf = s & (NSTAGE - 1);
        const __nv_bfloat16* ap = Ag + s * 32;
        const __nv_bfloat16* bp = Bg + s * 32;
        const uint32_t da = dstA + buf * STAGE_T;
        const uint32_t db = dstB + buf * STAGE_T;
#pragma unroll
        for (int i = 0; i < 2; i++) {
            CP_ASYNC16(da + i * 64 * RPAD_B, ap + (long long)(64 * i) * lda);
            CP_ASYNC16(db + i * 64 * RPAD_B, bp + (long long)(64 * i) * ldb);
        }
    };
    auto compute_stage = [&](int buf) {
        const uint32_t ab = a_off + buf * STAGE_T;
        const uint32_t bb = b_off + buf * STAGE_T;
#pragma unroll
        for (int kb = 0; kb < 2; kb++) {
            uint32_t afr[4][4], bfr[2][4];
#pragma unroll
            for (int mt = 0; mt < 4; mt++)
                LDSM_X4(afr[mt][0], afr[mt][1], afr[mt][2], afr[mt][3],
                        ab + mt * (16 * RPAD_B) + kb * 32);
#pragma unroll
            for (int t = 0; t < 2; t++)
                LDSM_X4(bfr[t][0], bfr[t][1], bfr[t][2], bfr[t][3],
                        bb + t * (16 * RPAD_B) + kb * 32);
#pragma unroll
            for (int mt = 0; mt < 4; mt++)
#pragma unroll
                for (int nt = 0; nt < 4; nt++)
                    mma_bf16(acc[mt][nt], afr[mt],
                             bfr[nt >> 1][nt & 1], bfr[nt >> 1][2 + (nt & 1)]);
        }
    };

    const int nst = K >> 5;
#pragma unroll
    for (int s = 0; s < NSTAGE - 1; s++) { issue_stage(s); CP_COMMIT(); }
    for (int s = 0; s < nst; s++) {
        CP_WAIT(NSTAGE - 2);
        __syncthreads();
        if (s + NSTAGE - 1 < nst) issue_stage(s + NSTAGE - 1);
        CP_COMMIT();
        compute_stage(s & (NSTAGE - 1));
    }

    const int lr  = l >> 2;
    const int lc2 = (l & 3) * 2;
#pragma unroll
    for (int mt = 0; mt < 4; mt++) {
        const int rA = wm * 64 + mt * 16 + lr;
#pragma unroll
        for (int nt = 0; nt < 4; nt++) {
            const int cA = wn * 32 + nt * 8 + lc2;
            *(uint16_t*)(C + cbase + (long long)rA * ldc + cA) =
                f2_to_fp8x2(acc[mt][nt][0] * alpha, acc[mt][nt][1] * alpha);
            *(uint16_t*)(C + cbase + (long long)(rA + 8) * ldc + cA) =
                f2_to_fp8x2(acc[mt][nt][2] * alpha, acc[mt][nt][3] * alpha);
        }
    }
}

// ===================== fp8 GEMM =====================
// MODE 0: C = fp8(alpha * A@B^T)                       (y, u)
// MODE 1: C = fp8(8*exp(alpha*acc + c2[col])); rs += row sums   (scores)
// MODE 2: C = f32(acc/rs[row] + bias2[col] + X_resid)  (final pre-LN)
template<int MODE>
__global__ __launch_bounds__(256) void mma_gemm_f8(
    const uint8_t* __restrict__ A, const uint8_t* __restrict__ B,
    void* __restrict__ Cv, float* __restrict__ rs,
    const float* __restrict__ c2, const float* __restrict__ bias2,
    const float* __restrict__ resid,
    int K, int lda, int ldb, int ldc,
    long long sA, long long sB, long long sC, float alpha)
{
    extern __shared__ char smem[];
    const uint32_t sb = smem_u32(smem);
    const int tid = threadIdx.x;
    const int wid = tid >> 5;
    const int l   = tid & 31;
    const int wm  = wid & 1;
    const int wn  = wid >> 1;
    const int bz  = blockIdx.z;
    const int row0 = blockIdx.y * 128;
    const int col0 = blockIdx.x * 128;

    A += (long long)bz * sA + (long long)row0 * lda;
    B += (long long)bz * sB + (long long)col0 * ldb;
    const long long cbase = (long long)bz * sC + (long long)row0 * ldc + col0;
    float* rsp = rs ? (rs + (long long)bz * Nq + row0) : nullptr;
    const float* c2p = (MODE == 1) ? (c2 + (long long)bz * Nq + col0) : nullptr;
    const float* Rp = (MODE == 2) ? (resid + cbase) : nullptr;

    const int r0  = tid >> 2;
    const int c16 = tid & 3;
    const uint8_t* Ag = A + (long long)r0 * lda + c16 * 16;
    const uint8_t* Bg = B + (long long)r0 * ldb + c16 * 16;
    const uint32_t dstA = sb + (uint32_t)(r0 * RPAD_B + c16 * 16);
    const uint32_t dstB = dstA + HALF_B;

    const uint32_t a_off = sb
        + (uint32_t)((wm * 64 + (l & 15)) * RPAD_B + ((l >> 4) & 1) * 16);
    const uint32_t b_off = sb + HALF_B
        + (uint32_t)((wn * 32 + (l & 15)) * RPAD_B + ((l >> 4) & 1) * 16);

    float acc[4][4][4];
#pragma unroll
    for (int mt = 0; mt < 4; mt++)
#pragma unroll
        for (int nt = 0; nt < 4; nt++)
#pragma unroll
            for (int i = 0; i < 4; i++) acc[mt][nt][i] = 0.f;

    auto issue_stage = [&](int s) {
        const int buf = s & (NSTAGE - 1);
        const uint8_t* ap = Ag + s * 64;
        const uint8_t* bp = Bg + s * 64;
        const uint32_t da = dstA + buf * STAGE_T;
        const uint32_t db = dstB + buf * STAGE_T;
#pragma unroll
        for (int i = 0; i < 2; i++) {
            CP_ASYNC16(da + i * 64 * RPAD_B, ap + (long long)(64 * i) * lda);
            CP_ASYNC16(db + i * 64 * RPAD_B, bp + (long long)(64 * i) * ldb);
        }
    };
    auto compute_stage = [&](int buf) {
        const uint32_t ab = a_off + buf * STAGE_T;
        const uint32_t bb = b_off + buf * STAGE_T;
#pragma unroll
        for (int kb = 0; kb < 2; kb++) {
            uint32_t afr[4][4], bfr[2][4];
#pragma unroll
            for (int mt = 0; mt < 4; mt++)
                LDSM_X4(afr[mt][0], afr[mt][1], afr[mt][2], afr[mt][3],
                        ab + mt * (16 * RPAD_B) + kb * 32);
#pragma unroll
            for (int t = 0; t < 2; t++)
                LDSM_X4(bfr[t][0], bfr[t][1], bfr[t][2], bfr[t][3],
                        bb + t * (16 * RPAD_B) + kb * 32);
#pragma unroll
            for (int mt = 0; mt < 4; mt++)
#pragma unroll
                for (int nt = 0; nt < 4; nt++)
                    mma_fp8(acc[mt][nt], afr[mt],
                            bfr[nt >> 1][nt & 1], bfr[nt >> 1][2 + (nt & 1)]);
        }
    };

    const int nst = K >> 6;
#pragma unroll
    for (int s = 0; s < NSTAGE - 1; s++) { issue_stage(s); CP_COMMIT(); }
    for (int s = 0; s < nst; s++) {
        CP_WAIT(NSTAGE - 2);
        __syncthreads();
        if (s + NSTAGE - 1 < nst) issue_stage(s + NSTAGE - 1);
        CP_COMMIT();
        compute_stage(s & (NSTAGE - 1));
    }

    uint8_t* C8 = (uint8_t*)Cv;
    float* Cf = (float*)Cv;
    const int lr  = l >> 2;
    const int lc2 = (l & 3) * 2;
#pragma unroll
    for (int mt = 0; mt < 4; mt++) {
        const int rA = wm * 64 + mt * 16 + lr;
        float sl = 0.f, sh = 0.f;
        float invl = 1.f, invh = 1.f;
        if (MODE == 2) { invl = 1.f / rsp[rA]; invh = 1.f / rsp[rA + 8]; }
#pragma unroll
        for (int nt = 0; nt < 4; nt++) {
            const int cA = wn * 32 + nt * 8 + lc2;
            float2 v0, v1;
            v0.x = acc[mt][nt][0] * alpha; v0.y = acc[mt][nt][1] * alpha;
            v1.x = acc[mt][nt][2] * alpha; v1.y = acc[mt][nt][3] * alpha;
            if (MODE == 0) {
                *(uint16_t*)(C8 + cbase + (long long)rA * ldc + cA) =
                    f2_to_fp8x2(v0.x, v0.y);
                *(uint16_t*)(C8 + cbase + (long long)(rA + 8) * ldc + cA) =
                    f2_to_fp8x2(v1.x, v1.y);
            } else if (MODE == 1) {
                float2 cc = *(const float2*)(c2p + cA);
                v0.x = __expf(v0.x + cc.x) * 8.f;
                v0.y = __expf(v0.y + cc.y) * 8.f;
                v1.x = __expf(v1.x + cc.x) * 8.f;
                v1.y = __expf(v1.y + cc.y) * 8.f;
                sl += v0.x + v0.y;
                sh += v1.x + v1.y;
                *(uint16_t*)(C8 + cbase + (long long)rA * ldc + cA) =
                    f2_to_fp8x2(v0.x, v0.y);
                *(uint16_t*)(C8 + cbase + (long long)(rA + 8) * ldc + cA) =
                    f2_to_fp8x2(v1.x, v1.y);
            } else {
                float2 bb2 = *(const float2*)(bias2 + col0 + cA);
                float2 q0 = *(const float2*)(Rp + (long long)rA * ldc + cA);
                float2 q1 = *(const float2*)(Rp + (long long)(rA + 8) * ldc + cA);
                v0.x = v0.x * invl + bb2.x + q0.x;
                v0.y = v0.y * invl + bb2.y + q0.y;
                v1.x = v1.x * invh + bb2.x + q1.x;
                v1.y = v1.y * invh + bb2.y + q1.y;
                *(float2*)(Cf + cbase + (long long)rA * ldc + cA) = v0;
                *(float2*)(Cf + cbase + (long long)(rA + 8) * ldc + cA) = v1;
            }
        }
        if (MODE == 1) {
            sl += __shfl_xor_sync(0xFFFFFFFF, sl, 1);
            sl += __shfl_xor_sync(0xFFFFFFFF, sl, 2);
            sh += __shfl_xor_sync(0xFFFFFFFF, sh, 1);
            sh += __shfl_xor_sync(0xFFFFFFFF, sh, 2);
            if ((l & 3) == 0) {
                atomicAdd(&rsp[rA], sl);
                atomicAdd(&rsp[rA + 8], sh);
            }
        }
    }
}

// ---------------- X -> fp8 ----------------
__global__ __launch_bounds__(256) void cvt_x8_k(const float* __restrict__ X,
                                                uint8_t* __restrict__ X8)
{
    const size_t i = ((size_t)blockIdx.x * 256 + threadIdx.x) * 8;
    float4 a = *(const float4*)(X + i);
    float4 b = *(const float4*)(X + i + 4);
    uint16_t w0 = f2_to_fp8x2(a.x, a.y);
    uint16_t w1 = f2_to_fp8x2(a.z, a.w);
    uint16_t w2 = f2_to_fp8x2(b.x, b.y);
    uint16_t w3 = f2_to_fp8x2(b.z, b.w);
    uint2 p;
    p.x = (uint32_t)w0 | ((uint32_t)w1 << 16);
    p.y = (uint32_t)w2 | ((uint32_t)w3 << 16);
    *(uint2*)(X8 + i) = p;
}

// ---------------- weights -> bf16: Wq, Wk, Wv plain cvt; WoT transpose ----------------
__global__ __launch_bounds__(256) void cvt_w_k(
    const float* __restrict__ wq, const float* __restrict__ wk,
    const float* __restrict__ wv, __nv_bfloat16* __restrict__ out)
{
    const int z = blockIdx.y;
    const float* W = (z == 0) ? wq : (z == 1) ? wk : wv;
    __nv_bfloat16* O = out + (size_t)z * Dq * Hq;
    const size_t i = ((size_t)blockIdx.x * 256 + threadIdx.x) * 4;
    float4 v = *(const float4*)(W + i);
    *(__nv_bfloat162*)(O + i)     = __float22bfloat162_rn(make_float2(v.x, v.y));
    *(__nv_bfloat162*)(O + i + 2) = __float22bfloat162_rn(make_float2(v.z, v.w));
}
__global__ __launch_bounds__(256) void transpose_wo_k(
    const float* __restrict__ wo, __nv_bfloat16* __restrict__ O)
{
    __shared__ float t[32][33];
    const int tx = threadIdx.x & 31;
    const int ty = threadIdx.x >> 5;
    const int x = blockIdx.x * 32 + tx;
    const int y0 = blockIdx.y * 32;
#pragma unroll
    for (int i = ty; i < 32; i += 8) t[i][tx] = wo[(y0 + i) * Dq + x];
    __syncthreads();
    const int ox = blockIdx.y * 32 + tx;
#pragma unroll
    for (int i = ty; i < 32; i += 8)
        O[(blockIdx.x * 32 + i) * Hq + ox] = __float2bfloat16_rn(t[tx][i]);
}

// ---------------- tiny bias kernels ----------------
// g1[i] = sum_h Wk[i,h] * bq[h]     (one warp per output)
__global__ __launch_bounds__(256) void gemv_g1_k(const float* __restrict__ Wk,
                                                 const float* __restrict__ bq,
                                                 float* __restrict__ g1)
{
    const int w = (blockIdx.x * 256 + threadIdx.x) >> 5;   // 0..511
    const int l = threadIdx.x & 31;
    float s = 0.f;
    for (int h = l; h < Hq; h += 32) s += Wk[w * Hq + h] * bq[h];
#pragma unroll
    for (int o = 16; o > 0; o >>= 1) s += __shfl_xor_sync(0xFFFFFFFF, s, o);
    if (l == 0) g1[w] = s;
}
// bias2[o] = bo[o] + sum_h bv[h]*Wo[h,o]
__global__ __launch_bounds__(256) void bias2_k(const float* __restrict__ Wo,
                                               const float* __restrict__ bv,
                                               const float* __restrict__ bo,
                                               float* __restrict__ bias2)
{
    const int o = blockIdx.x * 256 + threadIdx.x;
    float s = bo[o];
    for (int h = 0; h < Hq; h++) s += bv[h] * Wo[h * Dq + o];
    bias2[o] = s;
}
// c2s[m] = (X[m,:] . g1) / sqrt(H)   (one warp per row)
__global__ __launch_bounds__(256) void c2_k(const float* __restrict__ X,
                                            const float* __restrict__ g1,
                                            float* __restrict__ c2s)
{
    const int m = (blockIdx.x * 256 + threadIdx.x) >> 5;
    const int l = threadIdx.x & 31;
    const float* p = X + (long long)m * Dq;
    float s = 0.f;
#pragma unroll
    for (int i = 0; i < 4; i++) {
        int idx = l * 4 + i * 128;
        float4 xv = *(const float4*)(p + idx);
        float4 gv = *(const float4*)(g1 + idx);
        s += xv.x * gv.x + xv.y * gv.y + xv.z * gv.z + xv.w * gv.w;
    }
#pragma unroll
    for (int o = 16; o > 0; o >>= 1) s += __shfl_xor_sync(0xFFFFFFFF, s, o);
    if (l == 0) c2s[m] = s * 0.04419417382415922f;
}

// ---------------- LayerNorm over last dim (512) ----------------
__global__ __launch_bounds__(256) void ln_k(
    const float* __restrict__ in, const float* __restrict__ gamma,
    const float* __restrict__ beta, float* __restrict__ out)
{
    __shared__ float red[256];
    const float* p = in + blockIdx.x * (long long)Dq;
    const int t = threadIdx.x;
    float a = p[t], b = p[t + 256];
    red[t] = a + b; __syncthreads();
    for (int s = 128; s > 0; s >>= 1) { if (t < s) red[t] += red[t + s]; __syncthreads(); }
    const float mu = red[0] * (1.f / Dq); __syncthreads();
    float da = a - mu, db = b - mu;
    red[t] = da * da + db * db; __syncthreads();
    for (int s = 128; s > 0; s >>= 1) { if (t < s) red[t] += red[t + s]; __syncthreads(); }
    const float inv = rsqrtf(red[0] * (1.f / Dq) + 1e-5f);
    out[blockIdx.x * (long long)Dq + t]       = da * inv * gamma[t]       + beta[t];
    out[blockIdx.x * (long long)Dq + t + 256] = db * inv * gamma[t + 256] + beta[t + 256];
}

// ---------------- launch ----------------
extern "C" void kernel_launch(void* const* d_in, const int* in_sizes, int n_in,
                              void* d_out, int out_size)
{
    const float* X   = (const float*)d_in[0];
    const float* Wq  = (const float*)d_in[1];
    const float* bqp = (const float*)d_in[2];
    const float* Wk  = (const float*)d_in[3];
    const float* bkp = (const float*)d_in[4];   // (bk cancels in softmax rows)
    const float* Wv  = (const float*)d_in[5];
    const float* bvp = (const float*)d_in[6];
    const float* Wo  = (const float*)d_in[7];
    const float* bop = (const float*)d_in[8];
    const float* ga  = (const float*)d_in[9];
    const float* be  = (const float*)d_in[10];
    float* out = (float*)d_out;
    (void)bkp;

    void *px8, *py8, *pu8T, *pe8, *prs, *pwb, *pwpp8, *pwp8, *pg1, *pc2s, *pb2, *ptmp;
    cudaGetSymbolAddress(&px8, g_x8);
    cudaGetSymbolAddress(&py8, g_y8);
    cudaGetSymbolAddress(&pu8T, g_u8T);
    cudaGetSymbolAddress(&pe8, g_e8);
    cudaGetSymbolAddress(&prs, g_rs);
    cudaGetSymbolAddress(&pwb, g_wb);
    cudaGetSymbolAddress(&pwpp8, g_wpp8);
    cudaGetSymbolAddress(&pwp8, g_wp8);
    cudaGetSymbolAddress(&pg1, g_g1);
    cudaGetSymbolAddress(&pc2s, g_c2s);
    cudaGetSymbolAddress(&pb2, g_bias2);
    cudaGetSymbolAddress(&ptmp, g_tmp);
    uint8_t* x8   = (uint8_t*)px8;
    uint8_t* y8   = (uint8_t*)py8;
    uint8_t* u8T  = (uint8_t*)pu8T;
    uint8_t* e8   = (uint8_t*)pe8;
    float*   rs   = (float*)prs;
    __nv_bfloat16* wb = (__nv_bfloat16*)pwb;
    uint8_t* wpp8 = (uint8_t*)pwpp8;
    uint8_t* wp8  = (uint8_t*)pwp8;
    float*   g1   = (float*)pg1;
    float*   c2s  = (float*)pc2s;
    float*   b2   = (float*)pb2;
    float*   tmp  = (float*)ptmp;
    __nv_bfloat16* Wq_b  = wb;
    __nv_bfloat16* Wk_b  = wb + (size_t)Dq * Hq;
    __nv_bfloat16* Wv_b  = wb + (size_t)2 * Dq * Hq;
    __nv_bfloat16* WoT_b = wb + (size_t)3 * Dq * Hq;

    cudaFuncSetAttribute(mma_gemm_w,      cudaFuncAttributeMaxDynamicSharedMemorySize, SMEM_TOTAL);
    cudaFuncSetAttribute(mma_gemm_f8<0>,  cudaFuncAttributeMaxDynamicSharedMemorySize, SMEM_TOTAL);
    cudaFuncSetAttribute(mma_gemm_f8<1>,  cudaFuncAttributeMaxDynamicSharedMemorySize, SMEM_TOTAL);
    cudaFuncSetAttribute(mma_gemm_f8<2>,  cudaFuncAttributeMaxDynamicSharedMemorySize, SMEM_TOTAL);

    const float inv_sqrt_h = 0.04419417382415922f;  // 1/sqrt(512)
    dim3 blk(256);

    // 0. prep
    cudaMemsetAsync(rs, 0, (size_t)ROWS * sizeof(float));
    cvt_x8_k<<<(ROWS * Dq) / (256 * 8), blk>>>(X, x8);
    cvt_w_k<<<dim3((Dq * Hq) / (256 * 4), 3), blk>>>(Wq, Wk, Wv, wb);
    transpose_wo_k<<<dim3(16, 16), blk>>>(Wo, WoT_b);
    gemv_g1_k<<<64, blk>>>(Wk, bqp, g1);
    bias2_k<<<2, blk>>>(Wo, bvp, bop, b2);
    c2_k<<<ROWS / 8, blk>>>(X, g1, c2s);

    // 1. W''T*16 = 16 * (Wq @ Wk^T)^T : C[o,i] = sum_h Wk[o,h] Wq[i,h]
    mma_gemm_w<<<dim3(4, 4, 1), blk, SMEM_TOTAL>>>(Wk_b, Wq_b, wpp8,
                                                   Hq, Hq, Hq, Dq, 16.f);
    // 2. W'T*16 = 16 * (Wv @ Wo)^T : C[o,i] = sum_h WoT[o,h] Wv[i,h]
    mma_gemm_w<<<dim3(4, 4, 1), blk, SMEM_TOTAL>>>(WoT_b, Wv_b, wp8,
                                                   Hq, Hq, Hq, Dq, 16.f);
    // 3. y8 = fp8( (x8 @ W''T^T) / 16 )   [M=ROWS, N=512, K=512]
    mma_gemm_f8<0><<<dim3(Dq / 128, ROWS / 128, 1), blk, SMEM_TOTAL>>>(
        x8, wpp8, y8, nullptr, nullptr, nullptr, nullptr,
        Dq, Dq, Dq, Dq, 0, 0, 0, 1.f / 16.f);
    // 4. u8T = fp8( (W'T @ x8^T) / 16 )   [M=512, N=ROWS, K=512]
    mma_gemm_f8<0><<<dim3(ROWS / 128, Dq / 128, 1), blk, SMEM_TOTAL>>>(
        wp8, x8, u8T, nullptr, nullptr, nullptr, nullptr,
        Dq, Dq, Dq, ROWS, 0, 0, 0, 1.f / 16.f);
    // 5. e8 = fp8(8*exp(y8 @ x8^T / sqrt(H) + c2s[m])); rs += row sums
    mma_gemm_f8<1><<<dim3(Nq / 128, Nq / 128, Bq), blk, SMEM_TOTAL>>>(
        y8, x8, e8, rs, c2s, nullptr, nullptr,
        Dq, Dq, Dq, Nq,
        (long long)Nq * Dq, (long long)Nq * Dq, (long long)Nq * Nq, inv_sqrt_h);
    // 6. tmp = (e8 @ u8T)/rs + bias2[col] + X   [final pre-LN, fp32]
    mma_gemm_f8<2><<<dim3(Dq / 128, Nq / 128, Bq), blk, SMEM_TOTAL>>>(
        e8, u8T, tmp, rs, nullptr, b2, X,
        Nq, Nq, ROWS, Dq,
        (long long)Nq * Nq, (long long)Nq, (long long)Nq * Dq, 1.f);
    // 7. LayerNorm
    ln_k<<<ROWS, blk>>>(tmp, ga, be, out);
}

// round 10
// speedup vs baseline: 1.2177x; 1.0978x over previous
#include <cuda_runtime.h>
#include <cuda_bf16.h>
#include <cuda_fp8.h>
#include <cstdint>
#include <math_constants.h>

// ---------------- problem constants ----------------
#define Bq 8
#define Nq 2048
#define Dq 512
#define Hq 512
#define ROWS (Bq * Nq)          // 16384

// ---------------- scratch (device globals) ----------------
__device__ uint8_t g_x8[(size_t)ROWS * Dq];              // X in fp8
__device__ uint8_t g_y8[(size_t)ROWS * Dq];              // y = X@W'' fp8
__device__ uint8_t g_u8T[(size_t)Dq * ROWS];             // u^T = (X@W')^T fp8
__device__ uint8_t g_e8[(size_t)Bq * Nq * Nq];           // exp(scores)*8 fp8
__device__ float g_rs[(size_t)ROWS];                     // row sums of 8*exp
__device__ __nv_bfloat16 g_wb[(size_t)4 * Dq * Hq];      // Wq_b, Wk_b, Wv_b, WoT_b
__device__ uint8_t g_wpp8[(size_t)Dq * Dq];              // (W''^T)*16 fp8
__device__ uint8_t g_wp8[(size_t)Dq * Dq];               // (W'^T)*16 fp8
__device__ float g_g1[Dq];                               // Wk @ bq
__device__ float g_c2s[(size_t)ROWS];                    // (X @ g1)/sqrt(H)
__device__ float g_bias2[Dq];                            // bo + bv@Wo
__device__ float g_tmp[(size_t)ROWS * Dq];               // pre-LN fp32

// ---------------- helpers ----------------
__device__ __forceinline__ uint32_t smem_u32(const void* p) {
    uint32_t a;
    asm("{ .reg .u64 t; cvta.to.shared.u64 t, %1; cvt.u32.u64 %0, t; }" : "=r"(a) : "l"(p));
    return a;
}
#define LDSM_X4(r0, r1, r2, r3, addr) \
    asm volatile("ldmatrix.sync.aligned.m8n8.x4.shared.b16 {%0,%1,%2,%3}, [%4];" \
        : "=r"(r0), "=r"(r1), "=r"(r2), "=r"(r3) : "r"(addr))
#define CP_ASYNC16(dst, src) \
    asm volatile("cp.async.cg.shared.global [%0], [%1], 16;" :: "r"(dst), "l"(src))
#define CP_COMMIT() asm volatile("cp.async.commit_group;" ::: "memory")
#define CP_WAIT(n)  asm volatile("cp.async.wait_group %0;" :: "n"(n) : "memory")

__device__ __forceinline__ void mma_bf16(float* d, const uint32_t* a,
                                         uint32_t b0, uint32_t b1) {
    asm volatile(
        "mma.sync.aligned.m16n8k16.row.col.f32.bf16.bf16.f32 "
        "{%0,%1,%2,%3}, {%4,%5,%6,%7}, {%8,%9}, {%0,%1,%2,%3};"
        : "+f"(d[0]), "+f"(d[1]), "+f"(d[2]), "+f"(d[3])
        : "r"(a[0]), "r"(a[1]), "r"(a[2]), "r"(a[3]), "r"(b0), "r"(b1));
}
__device__ __forceinline__ void mma_fp8(float* d, const uint32_t* a,
                                        uint32_t b0, uint32_t b1) {
    asm volatile(
        "mma.sync.aligned.m16n8k32.row.col.f32.e4m3.e4m3.f32 "
        "{%0,%1,%2,%3}, {%4,%5,%6,%7}, {%8,%9}, {%0,%1,%2,%3};"
        : "+f"(d[0]), "+f"(d[1]), "+f"(d[2]), "+f"(d[3])
        : "r"(a[0]), "r"(a[1]), "r"(a[2]), "r"(a[3]), "r"(b0), "r"(b1));
}
__device__ __forceinline__ uint16_t f2_to_fp8x2(float x, float y) {
    return (uint16_t)__nv_cvt_float2_to_fp8x2(make_float2(x, y),
                                              __NV_SATFINITE, __NV_E4M3);
}

// ---------------- shared tiling constants ----------------
#define RPAD_B 80
#define HALF_B (128 * RPAD_B)                     // 10240
#define STAGE_T (2 * HALF_B)                      // 20480
#define NSTAGE 4
#define SMEM_TOTAL (NSTAGE * STAGE_T)             // 81920 (dynamic)

// ===================== bf16 GEMM, batched z=2 (weight products) =====================
// z=0: C0 = 16*(A0 @ B0^T);  z=1: C1 = 16*(A1 @ B1^T).  All 512x512x512, fp8 out.
__global__ __launch_bounds__(256) void mma_gemm_w2(
    const __nv_bfloat16* __restrict__ A0, const __nv_bfloat16* __restrict__ B0,
    uint8_t* __restrict__ C0,
    const __nv_bfloat16* __restrict__ A1, const __nv_bfloat16* __restrict__ B1,
    uint8_t* __restrict__ C1)
{
    extern __shared__ char smem[];
    const uint32_t sb = smem_u32(smem);
    const int tid = threadIdx.x;
    const int wid = tid >> 5;
    const int l   = tid & 31;
    const int wm  = wid & 1;
    const int wn  = wid >> 1;
    const int row0 = blockIdx.y * 128;
    const int col0 = blockIdx.x * 128;

    const __nv_bfloat16* A = (blockIdx.z == 0) ? A0 : A1;
    const __nv_bfloat16* B = (blockIdx.z == 0) ? B0 : B1;
    uint8_t* C = (blockIdx.z == 0) ? C0 : C1;
    const int lda = Hq, ldb = Hq, ldc = Dq, K = Hq;
    const float alpha = 16.f;

    A += (long long)row0 * lda;
    B += (long long)col0 * ldb;
    const long long cbase = (long long)row0 * ldc + col0;

    const int r0  = tid >> 2;
    const int c16 = tid & 3;
    const __nv_bfloat16* Ag = A + (long long)r0 * lda + c16 * 8;
    const __nv_bfloat16* Bg = B + (long long)r0 * ldb + c16 * 8;
    const uint32_t dstA = sb + (uint32_t)(r0 * RPAD_B + c16 * 16);
    const uint32_t dstB = dstA + HALF_B;

    const uint32_t a_off = sb
        + (uint32_t)((wm * 64 + (l & 15)) * RPAD_B + ((l >> 4) & 1) * 16);
    const uint32_t b_off = sb + HALF_B
        + (uint32_t)((wn * 32 + (l & 15)) * RPAD_B + ((l >> 4) & 1) * 16);

    float acc[4][4][4];
#pragma unroll
    for (int mt = 0; mt < 4; mt++)
#pragma unroll
        for (int nt = 0; nt < 4; nt++)
#pragma unroll
            for (int i = 0; i < 4; i++) acc[mt][nt][i] = 0.f;

    auto issue_stage = [&](int s) {
        const int buf = s & (NSTAGE - 1);
        const __nv_bfloat16* ap = Ag + s * 32;
        const __nv_bfloat16* bp = Bg + s * 32;
        const uint32_t da = dstA + buf * STAGE_T;
        const uint32_t db = dstB + buf * STAGE_T;
#pragma unroll
        for (int i = 0; i < 2; i++) {
            CP_ASYNC16(da + i * 64 * RPAD_B, ap + (long long)(64 * i) * lda);
            CP_ASYNC16(db + i * 64 * RPAD_B, bp + (long long)(64 * i) * ldb);
        }
    };
    auto compute_stage = [&](int buf) {
        const uint32_t ab = a_off + buf * STAGE_T;
        const uint32_t bb = b_off + buf * STAGE_T;
#pragma unroll
        for (int kb = 0; kb < 2; kb++) {
            uint32_t afr[4][4], bfr[2][4];
#pragma unroll
            for (int mt = 0; mt < 4; mt++)
                LDSM_X4(afr[mt][0], afr[mt][1], afr[mt][2], afr[mt][3],
                        ab + mt * (16 * RPAD_B) + kb * 32);
#pragma unroll
            for (int t = 0; t < 2; t++)
                LDSM_X4(bfr[t][0], bfr[t][1], bfr[t][2], bfr[t][3],
                        bb + t * (16 * RPAD_B) + kb * 32);
#pragma unroll
            for (int mt = 0; mt < 4; mt++)
#pragma unroll
                for (int nt = 0; nt < 4; nt++)
                    mma_bf16(acc[mt][nt], afr[mt],
                             bfr[nt >> 1][nt & 1], bfr[nt >> 1][2 + (nt & 1)]);
        }
    };

    const int nst = K >> 5;
#pragma unroll
    for (int s = 0; s < NSTAGE - 1; s++) { issue_stage(s); CP_COMMIT(); }
    for (int s = 0; s < nst; s++) {
        CP_WAIT(NSTAGE - 2);
        __syncthreads();
        if (s + NSTAGE - 1 < nst) issue_stage(s + NSTAGE - 1);
        CP_COMMIT();
        compute_stage(s & (NSTAGE - 1));
    }

    const int lr  = l >> 2;
    const int lc2 = (l & 3) * 2;
#pragma unroll
    for (int mt = 0; mt < 4; mt++) {
        const int rA = wm * 64 + mt * 16 + lr;
#pragma unroll
        for (int nt = 0; nt < 4; nt++) {
            const int cA = wn * 32 + nt * 8 + lc2;
            *(uint16_t*)(C + cbase + (long long)rA * ldc + cA) =
                f2_to_fp8x2(acc[mt][nt][0] * alpha, acc[mt][nt][1] * alpha);
            *(uint16_t*)(C + cbase + (long long)(rA + 8) * ldc + cA) =
                f2_to_fp8x2(acc[mt][nt][2] * alpha, acc[mt][nt][3] * alpha);
        }
    }
}

// ===================== fp8 GEMM =====================
// MODE 0: C = fp8(alpha * A@B^T)                       (y, u)
// MODE 1: C = fp8(8*exp(alpha*acc + c2[col])); rs += row sums   (scores)
// MODE 2: C = f32(acc/rs[row] + bias2[col] + X_resid)  (final pre-LN)
template<int MODE>
__global__ __launch_bounds__(256) void mma_gemm_f8(
    const uint8_t* __restrict__ A, const uint8_t* __restrict__ B,
    void* __restrict__ Cv, float* __restrict__ rs,
    const float* __restrict__ c2, const float* __restrict__ bias2,
    const float* __restrict__ resid,
    int K, int lda, int ldb, int ldc,
    long long sA, long long sB, long long sC, float alpha)
{
    extern __shared__ char smem[];
    const uint32_t sb = smem_u32(smem);
    const int tid = threadIdx.x;
    const int wid = tid >> 5;
    const int l   = tid & 31;
    const int wm  = wid & 1;
    const int wn  = wid >> 1;
    const int bz  = blockIdx.z;
    const int row0 = blockIdx.y * 128;
    const int col0 = blockIdx.x * 128;

    A += (long long)bz * sA + (long long)row0 * lda;
    B += (long long)bz * sB + (long long)col0 * ldb;
    const long long cbase = (long long)bz * sC + (long long)row0 * ldc + col0;
    float* rsp = rs ? (rs + (long long)bz * Nq + row0) : nullptr;
    const float* c2p = (MODE == 1) ? (c2 + (long long)bz * Nq + col0) : nullptr;
    const float* Rp = (MODE == 2) ? (resid + cbase) : nullptr;

    const int r0  = tid >> 2;
    const int c16 = tid & 3;
    const uint8_t* Ag = A + (long long)r0 * lda + c16 * 16;
    const uint8_t* Bg = B + (long long)r0 * ldb + c16 * 16;
    const uint32_t dstA = sb + (uint32_t)(r0 * RPAD_B + c16 * 16);
    const uint32_t dstB = dstA + HALF_B;

    const uint32_t a_off = sb
        + (uint32_t)((wm * 64 + (l & 15)) * RPAD_B + ((l >> 4) & 1) * 16);
    const uint32_t b_off = sb + HALF_B
        + (uint32_t)((wn * 32 + (l & 15)) * RPAD_B + ((l >> 4) & 1) * 16);

    float acc[4][4][4];
#pragma unroll
    for (int mt = 0; mt < 4; mt++)
#pragma unroll
        for (int nt = 0; nt < 4; nt++)
#pragma unroll
            for (int i = 0; i < 4; i++) acc[mt][nt][i] = 0.f;

    auto issue_stage = [&](int s) {
        const int buf = s & (NSTAGE - 1);
        const uint8_t* ap = Ag + s * 64;
        const uint8_t* bp = Bg + s * 64;
        const uint32_t da = dstA + buf * STAGE_T;
        const uint32_t db = dstB + buf * STAGE_T;
#pragma unroll
        for (int i = 0; i < 2; i++) {
            CP_ASYNC16(da + i * 64 * RPAD_B, ap + (long long)(64 * i) * lda);
            CP_ASYNC16(db + i * 64 * RPAD_B, bp + (long long)(64 * i) * ldb);
        }
    };
    auto compute_stage = [&](int buf) {
        const uint32_t ab = a_off + buf * STAGE_T;
        const uint32_t bb = b_off + buf * STAGE_T;
#pragma unroll
        for (int kb = 0; kb < 2; kb++) {
            uint32_t afr[4][4], bfr[2][4];
#pragma unroll
            for (int mt = 0; mt < 4; mt++)
                LDSM_X4(afr[mt][0], afr[mt][1], afr[mt][2], afr[mt][3],
                        ab + mt * (16 * RPAD_B) + kb * 32);
#pragma unroll
            for (int t = 0; t < 2; t++)
                LDSM_X4(bfr[t][0], bfr[t][1], bfr[t][2], bfr[t][3],
                        bb + t * (16 * RPAD_B) + kb * 32);
#pragma unroll
            for (int mt = 0; mt < 4; mt++)
#pragma unroll
                for (int nt = 0; nt < 4; nt++)
                    mma_fp8(acc[mt][nt], afr[mt],
                            bfr[nt >> 1][nt & 1], bfr[nt >> 1][2 + (nt & 1)]);
        }
    };

    const int nst = K >> 6;
#pragma unroll
    for (int s = 0; s < NSTAGE - 1; s++) { issue_stage(s); CP_COMMIT(); }
    for (int s = 0; s < nst; s++) {
        CP_WAIT(NSTAGE - 2);
        __syncthreads();
        if (s + NSTAGE - 1 < nst) issue_stage(s + NSTAGE - 1);
        CP_COMMIT();
        compute_stage(s & (NSTAGE - 1));
    }

    uint8_t* C8 = (uint8_t*)Cv;
    float* Cf = (float*)Cv;
    const int lr  = l >> 2;
    const int lc2 = (l & 3) * 2;
#pragma unroll
    for (int mt = 0; mt < 4; mt++) {
        const int rA = wm * 64 + mt * 16 + lr;
        float sl = 0.f, sh = 0.f;
        float invl = 1.f, invh = 1.f;
        if (MODE == 2) { invl = 1.f / rsp[rA]; invh = 1.f / rsp[rA + 8]; }
#pragma unroll
        for (int nt = 0; nt < 4; nt++) {
            const int cA = wn * 32 + nt * 8 + lc2;
            float2 v0, v1;
            v0.x = acc[mt][nt][0] * alpha; v0.y = acc[mt][nt][1] * alpha;
            v1.x = acc[mt][nt][2] * alpha; v1.y = acc[mt][nt][3] * alpha;
            if (MODE == 0) {
                *(uint16_t*)(C8 + cbase + (long long)rA * ldc + cA) =
                    f2_to_fp8x2(v0.x, v0.y);
                *(uint16_t*)(C8 + cbase + (long long)(rA + 8) * ldc + cA) =
                    f2_to_fp8x2(v1.x, v1.y);
            } else if (MODE == 1) {
                float2 cc = *(const float2*)(c2p + cA);
                v0.x = __expf(v0.x + cc.x) * 8.f;
                v0.y = __expf(v0.y + cc.y) * 8.f;
                v1.x = __expf(v1.x + cc.x) * 8.f;
                v1.y = __expf(v1.y + cc.y) * 8.f;
                sl += v0.x + v0.y;
                sh += v1.x + v1.y;
                *(uint16_t*)(C8 + cbase + (long long)rA * ldc + cA) =
                    f2_to_fp8x2(v0.x, v0.y);
                *(uint16_t*)(C8 + cbase + (long long)(rA + 8) * ldc + cA) =
                    f2_to_fp8x2(v1.x, v1.y);
            } else {
                float2 bb2 = *(const float2*)(bias2 + col0 + cA);
                float2 q0 = *(const float2*)(Rp + (long long)rA * ldc + cA);
                float2 q1 = *(const float2*)(Rp + (long long)(rA + 8) * ldc + cA);
                v0.x = v0.x * invl + bb2.x + q0.x;
                v0.y = v0.y * invl + bb2.y + q0.y;
                v1.x = v1.x * invh + bb2.x + q1.x;
                v1.y = v1.y * invh + bb2.y + q1.y;
                *(float2*)(Cf + cbase + (long long)rA * ldc + cA) = v0;
                *(float2*)(Cf + cbase + (long long)(rA + 8) * ldc + cA) = v1;
            }
        }
        if (MODE == 1) {
            sl += __shfl_xor_sync(0xFFFFFFFF, sl, 1);
            sl += __shfl_xor_sync(0xFFFFFFFF, sl, 2);
            sh += __shfl_xor_sync(0xFFFFFFFF, sh, 1);
            sh += __shfl_xor_sync(0xFFFFFFFF, sh, 2);
            if ((l & 3) == 0) {
                atomicAdd(&rsp[rA], sl);
                atomicAdd(&rsp[rA + 8], sh);
            }
        }
    }
}

// ---------------- fused gemv: g1 and bias2 (grid 512 x 2, 128 thr) ----------------
// y=0: g1[o] = sum_h Wk[o,h]*bq[h]
// y=1: bias2[o] = bo[o] + sum_h bv[h]*Wo[h,o]
__global__ __launch_bounds__(128) void gemv2_k(
    const float* __restrict__ Wk, const float* __restrict__ bq,
    const float* __restrict__ Wo, const float* __restrict__ bv,
    const float* __restrict__ bo,
    float* __restrict__ g1, float* __restrict__ bias2)
{
    __shared__ float red[4];
    const int o = blockIdx.x;
    const int t = threadIdx.x;
    float s = 0.f;
    if (blockIdx.y == 0) {
#pragma unroll
        for (int i = 0; i < 4; i++) {
            int h = t + i * 128;
            s += Wk[o * Hq + h] * bq[h];
        }
    } else {
#pragma unroll
        for (int i = 0; i < 4; i++) {
            int h = t + i * 128;
            s += bv[h] * Wo[h * Dq + o];
        }
    }
#pragma unroll
    for (int off = 16; off > 0; off >>= 1) s += __shfl_xor_sync(0xFFFFFFFF, s, off);
    if ((t & 31) == 0) red[t >> 5] = s;
    __syncthreads();
    if (t == 0) {
        float tot = red[0] + red[1] + red[2] + red[3];
        if (blockIdx.y == 0) g1[o] = tot;
        else bias2[o] = bo[o] + tot;
    }
}

// ---------------- fused: X->fp8, c2s = (X.g1)/sqrt(H), rs=0 (2 rows/block) --------
__global__ __launch_bounds__(256) void cvt_x8_c2_k(
    const float* __restrict__ X, const float* __restrict__ g1,
    uint8_t* __restrict__ X8, float* __restrict__ c2s, float* __restrict__ rs)
{
    __shared__ float red[2][4];
    const int t = threadIdx.x;
    const int rloc = t >> 7;                       // 0..1
    const int ti = t & 127;
    const long long row = (long long)blockIdx.x * 2 + rloc;
    const float* p = X + row * Dq + ti * 4;
    float4 v = *(const float4*)p;
    float4 g = *(const float4*)(g1 + ti * 4);
    // fp8 convert + pack 4 bytes
    uint16_t w0 = f2_to_fp8x2(v.x, v.y);
    uint16_t w1 = f2_to_fp8x2(v.z, v.w);
    *(uint32_t*)(X8 + row * Dq + ti * 4) = (uint32_t)w0 | ((uint32_t)w1 << 16);
    // row dot with g1
    float s = v.x * g.x + v.y * g.y + v.z * g.z + v.w * g.w;
#pragma unroll
    for (int off = 16; off > 0; off >>= 1) s += __shfl_xor_sync(0xFFFFFFFF, s, off);
    if ((ti & 31) == 0) red[rloc][ti >> 5] = s;
    __syncthreads();
    if (ti == 0) {
        float tot = red[rloc][0] + red[rloc][1] + red[rloc][2] + red[rloc][3];
        c2s[row] = tot * 0.04419417382415922f;
        rs[row] = 0.f;
    }
}

// ---------------- weights -> bf16: Wq, Wk, Wv plain cvt; WoT transpose ----------------
__global__ __launch_bounds__(256) void cvt_w_k(
    const float* __restrict__ wq, const float* __restrict__ wk,
    const float* __restrict__ wv, __nv_bfloat16* __restrict__ out)
{
    const int z = blockIdx.y;
    const float* W = (z == 0) ? wq : (z == 1) ? wk : wv;
    __nv_bfloat16* O = out + (size_t)z * Dq * Hq;
    const size_t i = ((size_t)blockIdx.x * 256 + threadIdx.x) * 4;
    float4 v = *(const float4*)(W + i);
    *(__nv_bfloat162*)(O + i)     = __float22bfloat162_rn(make_float2(v.x, v.y));
    *(__nv_bfloat162*)(O + i + 2) = __float22bfloat162_rn(make_float2(v.z, v.w));
}
__global__ __launch_bounds__(256) void transpose_wo_k(
    const float* __restrict__ wo, __nv_bfloat16* __restrict__ O)
{
    __shared__ float t[32][33];
    const int tx = threadIdx.x & 31;
    const int ty = threadIdx.x >> 5;
    const int x = blockIdx.x * 32 + tx;
    const int y0 = blockIdx.y * 32;
#pragma unroll
    for (int i = ty; i < 32; i += 8) t[i][tx] = wo[(y0 + i) * Dq + x];
    __syncthreads();
    const int ox = blockIdx.y * 32 + tx;
#pragma unroll
    for (int i = ty; i < 32; i += 8)
        O[(blockIdx.x * 32 + i) * Hq + ox] = __float2bfloat16_rn(t[tx][i]);
}

// ---------------- LayerNorm over last dim (512) ----------------
__global__ __launch_bounds__(256) void ln_k(
    const float* __restrict__ in, const float* __restrict__ gamma,
    const float* __restrict__ beta, float* __restrict__ out)
{
    __shared__ float red[256];
    const float* p = in + blockIdx.x * (long long)Dq;
    const int t = threadIdx.x;
    float a = p[t], b = p[t + 256];
    red[t] = a + b; __syncthreads();
    for (int s = 128; s > 0; s >>= 1) { if (t < s) red[t] += red[t + s]; __syncthreads(); }
    const float mu = red[0] * (1.f / Dq); __syncthreads();
    float da = a - mu, db = b - mu;
    red[t] = da * da + db * db; __syncthreads();
    for (int s = 128; s > 0; s >>= 1) { if (t < s) red[t] += red[t + s]; __syncthreads(); }
    const float inv = rsqrtf(red[0] * (1.f / Dq) + 1e-5f);
    out[blockIdx.x * (long long)Dq + t]       = da * inv * gamma[t]       + beta[t];
    out[blockIdx.x * (long long)Dq + t + 256] = db * inv * gamma[t + 256] + beta[t + 256];
}

// ---------------- launch ----------------
extern "C" void kernel_launch(void* const* d_in, const int* in_sizes, int n_in,
                              void* d_out, int out_size)
{
    const float* X   = (const float*)d_in[0];
    const float* Wq  = (const float*)d_in[1];
    const float* bqp = (const float*)d_in[2];
    const float* Wk  = (const float*)d_in[3];
    const float* Wv  = (const float*)d_in[5];
    const float* bvp = (const float*)d_in[6];
    const float* Wo  = (const float*)d_in[7];
    const float* bop = (const float*)d_in[8];
    const float* ga  = (const float*)d_in[9];
    const float* be  = (const float*)d_in[10];
    float* out = (float*)d_out;

    void *px8, *py8, *pu8T, *pe8, *prs, *pwb, *pwpp8, *pwp8, *pg1, *pc2s, *pb2, *ptmp;
    cudaGetSymbolAddress(&px8, g_x8);
    cudaGetSymbolAddress(&py8, g_y8);
    cudaGetSymbolAddress(&pu8T, g_u8T);
    cudaGetSymbolAddress(&pe8, g_e8);
    cudaGetSymbolAddress(&prs, g_rs);
    cudaGetSymbolAddress(&pwb, g_wb);
    cudaGetSymbolAddress(&pwpp8, g_wpp8);
    cudaGetSymbolAddress(&pwp8, g_wp8);
    cudaGetSymbolAddress(&pg1, g_g1);
    cudaGetSymbolAddress(&pc2s, g_c2s);
    cudaGetSymbolAddress(&pb2, g_bias2);
    cudaGetSymbolAddress(&ptmp, g_tmp);
    uint8_t* x8   = (uint8_t*)px8;
    uint8_t* y8   = (uint8_t*)py8;
    uint8_t* u8T  = (uint8_t*)pu8T;
    uint8_t* e8   = (uint8_t*)pe8;
    float*   rs   = (float*)prs;
    __nv_bfloat16* wb = (__nv_bfloat16*)pwb;
    uint8_t* wpp8 = (uint8_t*)pwpp8;
    uint8_t* wp8  = (uint8_t*)pwp8;
    float*   g1   = (float*)pg1;
    float*   c2s  = (float*)pc2s;
    float*   b2   = (float*)pb2;
    float*   tmp  = (float*)ptmp;
    __nv_bfloat16* Wq_b  = wb;
    __nv_bfloat16* Wk_b  = wb + (size_t)Dq * Hq;
    __nv_bfloat16* Wv_b  = wb + (size_t)2 * Dq * Hq;
    __nv_bfloat16* WoT_b = wb + (size_t)3 * Dq * Hq;

    cudaFuncSetAttribute(mma_gemm_w2,     cudaFuncAttributeMaxDynamicSharedMemorySize, SMEM_TOTAL);
    cudaFuncSetAttribute(mma_gemm_f8<0>,  cudaFuncAttributeMaxDynamicSharedMemorySize, SMEM_TOTAL);
    cudaFuncSetAttribute(mma_gemm_f8<1>,  cudaFuncAttributeMaxDynamicSharedMemorySize, SMEM_TOTAL);
    cudaFuncSetAttribute(mma_gemm_f8<2>,  cudaFuncAttributeMaxDynamicSharedMemorySize, SMEM_TOTAL);

    const float inv_sqrt_h = 0.04419417382415922f;  // 1/sqrt(512)
    dim3 blk(256);

    // 0. prep (4 launches)
    gemv2_k<<<dim3(512, 2), 128>>>(Wk, bqp, Wo, bvp, bop, g1, b2);
    cvt_x8_c2_k<<<ROWS / 2, blk>>>(X, g1, x8, c2s, rs);
    cvt_w_k<<<dim3((Dq * Hq) / (256 * 4), 3), blk>>>(Wq, Wk, Wv, wb);
    transpose_wo_k<<<dim3(16, 16), blk>>>(Wo, WoT_b);

    // 1. batched weight products: z=0 W''T*16 = 16*(Wk_b @ Wq_b^T); z=1 W'T*16 = 16*(WoT_b @ Wv_b^T)
    mma_gemm_w2<<<dim3(4, 4, 2), blk, SMEM_TOTAL>>>(Wk_b, Wq_b, wpp8,
                                                    WoT_b, Wv_b, wp8);
    // 2. y8 = fp8( (x8 @ W''T^T) / 16 )
    mma_gemm_f8<0><<<dim3(Dq / 128, ROWS / 128, 1), blk, SMEM_TOTAL>>>(
        x8, wpp8, y8, nullptr, nullptr, nullptr, nullptr,
        Dq, Dq, Dq, Dq, 0, 0, 0, 1.f / 16.f);
    // 3. u8T = fp8( (W'T @ x8^T) / 16 )
    mma_gemm_f8<0><<<dim3(ROWS / 128, Dq / 128, 1), blk, SMEM_TOTAL>>>(
        wp8, x8, u8T, nullptr, nullptr, nullptr, nullptr,
        Dq, Dq, Dq, ROWS, 0, 0, 0, 1.f / 16.f);
    // 4. e8 = fp8(8*exp(y8 @ x8^T / sqrt(H) + c2s[m])); rs += row sums
    mma_gemm_f8<1><<<dim3(Nq / 128, Nq / 128, Bq), blk, SMEM_TOTAL>>>(
        y8, x8, e8, rs, c2s, nullptr, nullptr,
        Dq, Dq, Dq, Nq,
        (long long)Nq * Dq, (long long)Nq * Dq, (long long)Nq * Nq, inv_sqrt_h);
    // 5. tmp = (e8 @ u8T)/rs + bias2[col] + X   [final pre-LN, fp32]
    mma_gemm_f8<2><<<dim3(Dq / 128, Nq / 128, Bq), blk, SMEM_TOTAL>>>(
        e8, u8T, tmp, rs, nullptr, b2, X,
        Nq, Nq, ROWS, Dq,
        (long long)Nq * Nq, (long long)Nq, (long long)Nq * Dq, 1.f);
    // 6. LayerNorm
    ln_k<<<ROWS, blk>>>(tmp, ga, be, out);
}

// round 11
// speedup vs baseline: 1.3335x; 1.0951x over previous
#include <cuda_runtime.h>
#include <cuda_bf16.h>
#include <cuda_fp8.h>
#include <cstdint>
#include <math_constants.h>

// ---------------- problem constants ----------------
#define Bq 8
#define Nq 2048
#define Dq 512
#define Hq 512
#define ROWS (Bq * Nq)          // 16384

// ---------------- scratch (device globals) ----------------
__device__ uint8_t g_x8[(size_t)ROWS * Dq];              // X in fp8
__device__ uint8_t g_y8[(size_t)ROWS * Dq];              // y = X@W'' fp8
__device__ uint8_t g_u8T[(size_t)Dq * ROWS];             // u^T = (X@W')^T fp8
__device__ uint8_t g_e8[(size_t)Bq * Nq * Nq];           // exp(scores)*8 fp8
__device__ float g_rs[(size_t)ROWS];                     // row sums of 8*exp
__device__ __nv_bfloat16 g_wb[(size_t)4 * Dq * Hq];      // Wq_b, Wk_b, Wv_b, WoT_b
__device__ uint8_t g_wpp8[(size_t)Dq * Dq];              // (W''^T)*16 fp8
__device__ uint8_t g_wp8[(size_t)Dq * Dq];               // (W'^T)*16 fp8
__device__ float g_g1[Dq];                               // Wk @ bq
__device__ float g_c2s[(size_t)ROWS];                    // (X @ g1)/sqrt(H)
__device__ float g_bias2[Dq];                            // bo + bv@Wo
__device__ float g_tmp[(size_t)ROWS * Dq];               // pre-LN fp32

// ---------------- helpers ----------------
__device__ __forceinline__ uint32_t smem_u32(const void* p) {
    uint32_t a;
    asm("{ .reg .u64 t; cvta.to.shared.u64 t, %1; cvt.u32.u64 %0, t; }" : "=r"(a) : "l"(p));
    return a;
}
#define LDSM_X4(r0, r1, r2, r3, addr) \
    asm volatile("ldmatrix.sync.aligned.m8n8.x4.shared.b16 {%0,%1,%2,%3}, [%4];" \
        : "=r"(r0), "=r"(r1), "=r"(r2), "=r"(r3) : "r"(addr))
#define CP_ASYNC16(dst, src) \
    asm volatile("cp.async.cg.shared.global [%0], [%1], 16;" :: "r"(dst), "l"(src))
#define CP_COMMIT() asm volatile("cp.async.commit_group;" ::: "memory")
#define CP_WAIT(n)  asm volatile("cp.async.wait_group %0;" :: "n"(n) : "memory")

__device__ __forceinline__ void mma_bf16(float* d, const uint32_t* a,
                                         uint32_t b0, uint32_t b1) {
    asm volatile(
        "mma.sync.aligned.m16n8k16.row.col.f32.bf16.bf16.f32 "
        "{%0,%1,%2,%3}, {%4,%5,%6,%7}, {%8,%9}, {%0,%1,%2,%3};"
        : "+f"(d[0]), "+f"(d[1]), "+f"(d[2]), "+f"(d[3])
        : "r"(a[0]), "r"(a[1]), "r"(a[2]), "r"(a[3]), "r"(b0), "r"(b1));
}
__device__ __forceinline__ void mma_fp8(float* d, const uint32_t* a,
                                        uint32_t b0, uint32_t b1) {
    asm volatile(
        "mma.sync.aligned.m16n8k32.row.col.f32.e4m3.e4m3.f32 "
        "{%0,%1,%2,%3}, {%4,%5,%6,%7}, {%8,%9}, {%0,%1,%2,%3};"
        : "+f"(d[0]), "+f"(d[1]), "+f"(d[2]), "+f"(d[3])
        : "r"(a[0]), "r"(a[1]), "r"(a[2]), "r"(a[3]), "r"(b0), "r"(b1));
}
__device__ __forceinline__ uint16_t f2_to_fp8x2(float x, float y) {
    return (uint16_t)__nv_cvt_float2_to_fp8x2(make_float2(x, y),
                                              __NV_SATFINITE, __NV_E4M3);
}

// ---------------- shared tiling constants ----------------
#define RPAD_B 80
#define HALF_B (128 * RPAD_B)                     // 10240
#define STAGE_T (2 * HALF_B)                      // 20480
#define NSTAGE 4
#define SMEM_TOTAL (NSTAGE * STAGE_T)             // 81920 (dynamic)

// ===================== bf16 GEMM, batched z=2 (weight products) =====================
__global__ __launch_bounds__(256) void mma_gemm_w2(
    const __nv_bfloat16* __restrict__ A0, const __nv_bfloat16* __restrict__ B0,
    uint8_t* __restrict__ C0,
    const __nv_bfloat16* __restrict__ A1, const __nv_bfloat16* __restrict__ B1,
    uint8_t* __restrict__ C1)
{
    extern __shared__ char smem[];
    const uint32_t sb = smem_u32(smem);
    const int tid = threadIdx.x;
    const int wid = tid >> 5;
    const int l   = tid & 31;
    const int wm  = wid & 1;
    const int wn  = wid >> 1;
    const int row0 = blockIdx.y * 128;
    const int col0 = blockIdx.x * 128;

    const __nv_bfloat16* A = (blockIdx.z == 0) ? A0 : A1;
    const __nv_bfloat16* B = (blockIdx.z == 0) ? B0 : B1;
    uint8_t* C = (blockIdx.z == 0) ? C0 : C1;
    const int lda = Hq, ldb = Hq, ldc = Dq, K = Hq;
    const float alpha = 16.f;

    A += (long long)row0 * lda;
    B += (long long)col0 * ldb;
    const long long cbase = (long long)row0 * ldc + col0;

    const int r0  = tid >> 2;
    const int c16 = tid & 3;
    const __nv_bfloat16* Ag = A + (long long)r0 * lda + c16 * 8;
    const __nv_bfloat16* Bg = B + (long long)r0 * ldb + c16 * 8;
    const uint32_t dstA = sb + (uint32_t)(r0 * RPAD_B + c16 * 16);
    const uint32_t dstB = dstA + HALF_B;

    const uint32_t a_off = sb
        + (uint32_t)((wm * 64 + (l & 15)) * RPAD_B + ((l >> 4) & 1) * 16);
    const uint32_t b_off = sb + HALF_B
        + (uint32_t)((wn * 32 + (l & 15)) * RPAD_B + ((l >> 4) & 1) * 16);

    float acc[4][4][4];
#pragma unroll
    for (int mt = 0; mt < 4; mt++)
#pragma unroll
        for (int nt = 0; nt < 4; nt++)
#pragma unroll
            for (int i = 0; i < 4; i++) acc[mt][nt][i] = 0.f;

    auto issue_stage = [&](int s) {
        const int buf = s & (NSTAGE - 1);
        const __nv_bfloat16* ap = Ag + s * 32;
        const __nv_bfloat16* bp = Bg + s * 32;
        const uint32_t da = dstA + buf * STAGE_T;
        const uint32_t db = dstB + buf * STAGE_T;
#pragma unroll
        for (int i = 0; i < 2; i++) {
            CP_ASYNC16(da + i * 64 * RPAD_B, ap + (long long)(64 * i) * lda);
            CP_ASYNC16(db + i * 64 * RPAD_B, bp + (long long)(64 * i) * ldb);
        }
    };
    auto compute_stage = [&](int buf) {
        const uint32_t ab = a_off + buf * STAGE_T;
        const uint32_t bb = b_off + buf * STAGE_T;
#pragma unroll
        for (int kb = 0; kb < 2; kb++) {
            uint32_t afr[4][4], bfr[2][4];
#pragma unroll
            for (int mt = 0; mt < 4; mt++)
                LDSM_X4(afr[mt][0], afr[mt][1], afr[mt][2], afr[mt][3],
                        ab + mt * (16 * RPAD_B) + kb * 32);
#pragma unroll
            for (int t = 0; t < 2; t++)
                LDSM_X4(bfr[t][0], bfr[t][1], bfr[t][2], bfr[t][3],
                        bb + t * (16 * RPAD_B) + kb * 32);
#pragma unroll
            for (int mt = 0; mt < 4; mt++)
#pragma unroll
                for (int nt = 0; nt < 4; nt++)
                    mma_bf16(acc[mt][nt], afr[mt],
                             bfr[nt >> 1][nt & 1], bfr[nt >> 1][2 + (nt & 1)]);
        }
    };

    const int nst = K >> 5;
#pragma unroll
    for (int s = 0; s < NSTAGE - 1; s++) { issue_stage(s); CP_COMMIT(); }
    for (int s = 0; s < nst; s++) {
        CP_WAIT(NSTAGE - 2);
        __syncthreads();
        if (s + NSTAGE - 1 < nst) issue_stage(s + NSTAGE - 1);
        CP_COMMIT();
        compute_stage(s & (NSTAGE - 1));
    }

    const int lr  = l >> 2;
    const int lc2 = (l & 3) * 2;
#pragma unroll
    for (int mt = 0; mt < 4; mt++) {
        const int rA = wm * 64 + mt * 16 + lr;
#pragma unroll
        for (int nt = 0; nt < 4; nt++) {
            const int cA = wn * 32 + nt * 8 + lc2;
            *(uint16_t*)(C + cbase + (long long)rA * ldc + cA) =
                f2_to_fp8x2(acc[mt][nt][0] * alpha, acc[mt][nt][1] * alpha);
            *(uint16_t*)(C + cbase + (long long)(rA + 8) * ldc + cA) =
                f2_to_fp8x2(acc[mt][nt][2] * alpha, acc[mt][nt][3] * alpha);
        }
    }
}

// ===================== fp8 GEMM: y and u batched (z=2) =====================
// z=0: y8[M=ROWS,N=512] = fp8((x8 @ wpp^T)/16), row0=by*128, col0=bx*128
// z=1: u8T[M=512,N=ROWS] = fp8((wp @ x8^T)/16), row0=bx*128, col0=by*128
__global__ __launch_bounds__(256) void mma_gemm_f8_yu(
    const uint8_t* __restrict__ x8, const uint8_t* __restrict__ wpp,
    const uint8_t* __restrict__ wp,
    uint8_t* __restrict__ y8, uint8_t* __restrict__ u8T)
{
    extern __shared__ char smem[];
    const uint32_t sb = smem_u32(smem);
    const int tid = threadIdx.x;
    const int wid = tid >> 5;
    const int l   = tid & 31;
    const int wm  = wid & 1;
    const int wn  = wid >> 1;

    const uint8_t* A;
    const uint8_t* B;
    uint8_t* C;
    int ldc, row0, col0;
    if (blockIdx.z == 0) {
        A = x8; B = wpp; C = y8; ldc = Dq;
        row0 = blockIdx.y * 128; col0 = blockIdx.x * 128;
    } else {
        A = wp; B = x8; C = u8T; ldc = ROWS;
        row0 = blockIdx.x * 128; col0 = blockIdx.y * 128;
    }
    const int lda = Dq, ldb = Dq, K = Dq;
    const float alpha = 1.f / 16.f;

    A += (long long)row0 * lda;
    B += (long long)col0 * ldb;
    const long long cbase = (long long)row0 * ldc + col0;

    const int r0  = tid >> 2;
    const int c16 = tid & 3;
    const uint8_t* Ag = A + (long long)r0 * lda + c16 * 16;
    const uint8_t* Bg = B + (long long)r0 * ldb + c16 * 16;
    const uint32_t dstA = sb + (uint32_t)(r0 * RPAD_B + c16 * 16);
    const uint32_t dstB = dstA + HALF_B;

    const uint32_t a_off = sb
        + (uint32_t)((wm * 64 + (l & 15)) * RPAD_B + ((l >> 4) & 1) * 16);
    const uint32_t b_off = sb + HALF_B
        + (uint32_t)((wn * 32 + (l & 15)) * RPAD_B + ((l >> 4) & 1) * 16);

    float acc[4][4][4];
#pragma unroll
    for (int mt = 0; mt < 4; mt++)
#pragma unroll
        for (int nt = 0; nt < 4; nt++)
#pragma unroll
            for (int i = 0; i < 4; i++) acc[mt][nt][i] = 0.f;

    auto issue_stage = [&](int s) {
        const int buf = s & (NSTAGE - 1);
        const uint8_t* ap = Ag + s * 64;
        const uint8_t* bp = Bg + s * 64;
        const uint32_t da = dstA + buf * STAGE_T;
        const uint32_t db = dstB + buf * STAGE_T;
#pragma unroll
        for (int i = 0; i < 2; i++) {
            CP_ASYNC16(da + i * 64 * RPAD_B, ap + (long long)(64 * i) * lda);
            CP_ASYNC16(db + i * 64 * RPAD_B, bp + (long long)(64 * i) * ldb);
        }
    };
    auto compute_stage = [&](int buf) {
        const uint32_t ab = a_off + buf * STAGE_T;
        const uint32_t bb = b_off + buf * STAGE_T;
#pragma unroll
        for (int kb = 0; kb < 2; kb++) {
            uint32_t afr[4][4], bfr[2][4];
#pragma unroll
            for (int mt = 0; mt < 4; mt++)
                LDSM_X4(afr[mt][0], afr[mt][1], afr[mt][2], afr[mt][3],
                        ab + mt * (16 * RPAD_B) + kb * 32);
#pragma unroll
            for (int t = 0; t < 2; t++)
                LDSM_X4(bfr[t][0], bfr[t][1], bfr[t][2], bfr[t][3],
                        bb + t * (16 * RPAD_B) + kb * 32);
#pragma unroll
            for (int mt = 0; mt < 4; mt++)
#pragma unroll
                for (int nt = 0; nt < 4; nt++)
                    mma_fp8(acc[mt][nt], afr[mt],
                            bfr[nt >> 1][nt & 1], bfr[nt >> 1][2 + (nt & 1)]);
        }
    };

    const int nst = K >> 6;
#pragma unroll
    for (int s = 0; s < NSTAGE - 1; s++) { issue_stage(s); CP_COMMIT(); }
    for (int s = 0; s < nst; s++) {
        CP_WAIT(NSTAGE - 2);
        __syncthreads();
        if (s + NSTAGE - 1 < nst) issue_stage(s + NSTAGE - 1);
        CP_COMMIT();
        compute_stage(s & (NSTAGE - 1));
    }

    const int lr  = l >> 2;
    const int lc2 = (l & 3) * 2;
#pragma unroll
    for (int mt = 0; mt < 4; mt++) {
        const int rA = wm * 64 + mt * 16 + lr;
#pragma unroll
        for (int nt = 0; nt < 4; nt++) {
            const int cA = wn * 32 + nt * 8 + lc2;
            *(uint16_t*)(C + cbase + (long long)rA * ldc + cA) =
                f2_to_fp8x2(acc[mt][nt][0] * alpha, acc[mt][nt][1] * alpha);
            *(uint16_t*)(C + cbase + (long long)(rA + 8) * ldc + cA) =
                f2_to_fp8x2(acc[mt][nt][2] * alpha, acc[mt][nt][3] * alpha);
        }
    }
}

// ===================== fp8 GEMM (scores / final) =====================
// MODE 1: C = fp8(8*exp(alpha*acc + c2[col])); rs += row sums   (scores)
// MODE 2: C = f32(acc/rs[row] + bias2[col] + X_resid)           (final pre-LN)
template<int MODE>
__global__ __launch_bounds__(256) void mma_gemm_f8(
    const uint8_t* __restrict__ A, const uint8_t* __restrict__ B,
    void* __restrict__ Cv, float* __restrict__ rs,
    const float* __restrict__ c2, const float* __restrict__ bias2,
    const float* __restrict__ resid,
    int K, int lda, int ldb, int ldc,
    long long sA, long long sB, long long sC, float alpha)
{
    extern __shared__ char smem[];
    const uint32_t sb = smem_u32(smem);
    const int tid = threadIdx.x;
    const int wid = tid >> 5;
    const int l   = tid & 31;
    const int wm  = wid & 1;
    const int wn  = wid >> 1;
    const int bz  = blockIdx.z;
    const int row0 = blockIdx.y * 128;
    const int col0 = blockIdx.x * 128;

    A += (long long)bz * sA + (long long)row0 * lda;
    B += (long long)bz * sB + (long long)col0 * ldb;
    const long long cbase = (long long)bz * sC + (long long)row0 * ldc + col0;
    float* rsp = rs ? (rs + (long long)bz * Nq + row0) : nullptr;
    const float* c2p = (MODE == 1) ? (c2 + (long long)bz * Nq + col0) : nullptr;
    const float* Rp = (MODE == 2) ? (resid + cbase) : nullptr;

    const int r0  = tid >> 2;
    const int c16 = tid & 3;
    const uint8_t* Ag = A + (long long)r0 * lda + c16 * 16;
    const uint8_t* Bg = B + (long long)r0 * ldb + c16 * 16;
    const uint32_t dstA = sb + (uint32_t)(r0 * RPAD_B + c16 * 16);
    const uint32_t dstB = dstA + HALF_B;

    const uint32_t a_off = sb
        + (uint32_t)((wm * 64 + (l & 15)) * RPAD_B + ((l >> 4) & 1) * 16);
    const uint32_t b_off = sb + HALF_B
        + (uint32_t)((wn * 32 + (l & 15)) * RPAD_B + ((l >> 4) & 1) * 16);

    float acc[4][4][4];
#pragma unroll
    for (int mt = 0; mt < 4; mt++)
#pragma unroll
        for (int nt = 0; nt < 4; nt++)
#pragma unroll
            for (int i = 0; i < 4; i++) acc[mt][nt][i] = 0.f;

    auto issue_stage = [&](int s) {
        const int buf = s & (NSTAGE - 1);
        const uint8_t* ap = Ag + s * 64;
        const uint8_t* bp = Bg + s * 64;
        const uint32_t da = dstA + buf * STAGE_T;
        const uint32_t db = dstB + buf * STAGE_T;
#pragma unroll
        for (int i = 0; i < 2; i++) {
            CP_ASYNC16(da + i * 64 * RPAD_B, ap + (long long)(64 * i) * lda);
            CP_ASYNC16(db + i * 64 * RPAD_B, bp + (long long)(64 * i) * ldb);
        }
    };
    auto compute_stage = [&](int buf) {
        const uint32_t ab = a_off + buf * STAGE_T;
        const uint32_t bb = b_off + buf * STAGE_T;
#pragma unroll
        for (int kb = 0; kb < 2; kb++) {
            uint32_t afr[4][4], bfr[2][4];
#pragma unroll
            for (int mt = 0; mt < 4; mt++)
                LDSM_X4(afr[mt][0], afr[mt][1], afr[mt][2], afr[mt][3],
                        ab + mt * (16 * RPAD_B) + kb * 32);
#pragma unroll
            for (int t = 0; t < 2; t++)
                LDSM_X4(bfr[t][0], bfr[t][1], bfr[t][2], bfr[t][3],
                        bb + t * (16 * RPAD_B) + kb * 32);
#pragma unroll
            for (int mt = 0; mt < 4; mt++)
#pragma unroll
                for (int nt = 0; nt < 4; nt++)
                    mma_fp8(acc[mt][nt], afr[mt],
                            bfr[nt >> 1][nt & 1], bfr[nt >> 1][2 + (nt & 1)]);
        }
    };

    const int nst = K >> 6;
#pragma unroll
    for (int s = 0; s < NSTAGE - 1; s++) { issue_stage(s); CP_COMMIT(); }
    for (int s = 0; s < nst; s++) {
        CP_WAIT(NSTAGE - 2);
        __syncthreads();
        if (s + NSTAGE - 1 < nst) issue_stage(s + NSTAGE - 1);
        CP_COMMIT();
        compute_stage(s & (NSTAGE - 1));
    }

    uint8_t* C8 = (uint8_t*)Cv;
    float* Cf = (float*)Cv;
    const int lr  = l >> 2;
    const int lc2 = (l & 3) * 2;
#pragma unroll
    for (int mt = 0; mt < 4; mt++) {
        const int rA = wm * 64 + mt * 16 + lr;
        float sl = 0.f, sh = 0.f;
        float invl = 1.f, invh = 1.f;
        if (MODE == 2) { invl = 1.f / rsp[rA]; invh = 1.f / rsp[rA + 8]; }
#pragma unroll
        for (int nt = 0; nt < 4; nt++) {
            const int cA = wn * 32 + nt * 8 + lc2;
            float2 v0, v1;
            v0.x = acc[mt][nt][0] * alpha; v0.y = acc[mt][nt][1] * alpha;
            v1.x = acc[mt][nt][2] * alpha; v1.y = acc[mt][nt][3] * alpha;
            if (MODE == 1) {
                float2 cc = *(const float2*)(c2p + cA);
                v0.x = __expf(v0.x + cc.x) * 8.f;
                v0.y = __expf(v0.y + cc.y) * 8.f;
                v1.x = __expf(v1.x + cc.x) * 8.f;
                v1.y = __expf(v1.y + cc.y) * 8.f;
                sl += v0.x + v0.y;
                sh += v1.x + v1.y;
                *(uint16_t*)(C8 + cbase + (long long)rA * ldc + cA) =
                    f2_to_fp8x2(v0.x, v0.y);
                *(uint16_t*)(C8 + cbase + (long long)(rA + 8) * ldc + cA) =
                    f2_to_fp8x2(v1.x, v1.y);
            } else {
                float2 bb2 = *(const float2*)(bias2 + col0 + cA);
                float2 q0 = *(const float2*)(Rp + (long long)rA * ldc + cA);
                float2 q1 = *(const float2*)(Rp + (long long)(rA + 8) * ldc + cA);
                v0.x = v0.x * invl + bb2.x + q0.x;
                v0.y = v0.y * invl + bb2.y + q0.y;
                v1.x = v1.x * invh + bb2.x + q1.x;
                v1.y = v1.y * invh + bb2.y + q1.y;
                *(float2*)(Cf + cbase + (long long)rA * ldc + cA) = v0;
                *(float2*)(Cf + cbase + (long long)(rA + 8) * ldc + cA) = v1;
            }
        }
        if (MODE == 1) {
            sl += __shfl_xor_sync(0xFFFFFFFF, sl, 1);
            sl += __shfl_xor_sync(0xFFFFFFFF, sl, 2);
            sh += __shfl_xor_sync(0xFFFFFFFF, sh, 1);
            sh += __shfl_xor_sync(0xFFFFFFFF, sh, 2);
            if ((l & 3) == 0) {
                atomicAdd(&rsp[rA], sl);
                atomicAdd(&rsp[rA + 8], sh);
            }
        }
    }
}

// ---------------- fused gemv: g1 and bias2 (grid 512 x 2, 128 thr) ----------------
__global__ __launch_bounds__(128) void gemv2_k(
    const float* __restrict__ Wk, const float* __restrict__ bq,
    const float* __restrict__ Wo, const float* __restrict__ bv,
    const float* __restrict__ bo,
    float* __restrict__ g1, float* __restrict__ bias2)
{
    __shared__ float red[4];
    const int o = blockIdx.x;
    const int t = threadIdx.x;
    float s = 0.f;
    if (blockIdx.y == 0) {
#pragma unroll
        for (int i = 0; i < 4; i++) {
            int h = t + i * 128;
            s += Wk[o * Hq + h] * bq[h];
        }
    } else {
#pragma unroll
        for (int i = 0; i < 4; i++) {
            int h = t + i * 128;
            s += bv[h] * Wo[h * Dq + o];
        }
    }
#pragma unroll
    for (int off = 16; off > 0; off >>= 1) s += __shfl_xor_sync(0xFFFFFFFF, s, off);
    if ((t & 31) == 0) red[t >> 5] = s;
    __syncthreads();
    if (t == 0) {
        float tot = red[0] + red[1] + red[2] + red[3];
        if (blockIdx.y == 0) g1[o] = tot;
        else bias2[o] = bo[o] + tot;
    }
}

// ---------------- fused: X->fp8, c2s = (X.g1)/sqrt(H), rs=0 (2 rows/block) --------
__global__ __launch_bounds__(256) void cvt_x8_c2_k(
    const float* __restrict__ X, const float* __restrict__ g1,
    uint8_t* __restrict__ X8, float* __restrict__ c2s, float* __restrict__ rs)
{
    __shared__ float red[2][4];
    const int t = threadIdx.x;
    const int rloc = t >> 7;                       // 0..1
    const int ti = t & 127;
    const long long row = (long long)blockIdx.x * 2 + rloc;
    const float* p = X + row * Dq + ti * 4;
    float4 v = *(const float4*)p;
    float4 g = *(const float4*)(g1 + ti * 4);
    uint16_t w0 = f2_to_fp8x2(v.x, v.y);
    uint16_t w1 = f2_to_fp8x2(v.z, v.w);
    *(uint32_t*)(X8 + row * Dq + ti * 4) = (uint32_t)w0 | ((uint32_t)w1 << 16);
    float s = v.x * g.x + v.y * g.y + v.z * g.z + v.w * g.w;
#pragma unroll
    for (int off = 16; off > 0; off >>= 1) s += __shfl_xor_sync(0xFFFFFFFF, s, off);
    if ((ti & 31) == 0) red[rloc][ti >> 5] = s;
    __syncthreads();
    if (ti == 0) {
        float tot = red[rloc][0] + red[rloc][1] + red[rloc][2] + red[rloc][3];
        c2s[row] = tot * 0.04419417382415922f;
        rs[row] = 0.f;
    }
}

// ---------------- fused weight prep: z<3 convert Wq/Wk/Wv; z=3 transpose Wo -------
__global__ __launch_bounds__(256) void wprep_k(
    const float* __restrict__ wq, const float* __restrict__ wk,
    const float* __restrict__ wv, const float* __restrict__ wo,
    __nv_bfloat16* __restrict__ out)
{
    const int z = blockIdx.z;
    if (z < 3) {
        const float* W = (z == 0) ? wq : (z == 1) ? wk : wv;
        __nv_bfloat16* O = out + (size_t)z * Dq * Hq;
        const size_t i = (((size_t)blockIdx.y * 16 + blockIdx.x) * 256 + threadIdx.x) * 4;
        float4 v = *(const float4*)(W + i);
        *(__nv_bfloat162*)(O + i)     = __float22bfloat162_rn(make_float2(v.x, v.y));
        *(__nv_bfloat162*)(O + i + 2) = __float22bfloat162_rn(make_float2(v.z, v.w));
    } else {
        __shared__ float t[32][33];
        __nv_bfloat16* O = out + (size_t)3 * Dq * Hq;
        const int tx = threadIdx.x & 31;
        const int ty = threadIdx.x >> 5;
        const int x = blockIdx.x * 32 + tx;
        const int y0 = blockIdx.y * 32;
#pragma unroll
        for (int i = ty; i < 32; i += 8) t[i][tx] = wo[(y0 + i) * Dq + x];
        __syncthreads();
        const int ox = blockIdx.y * 32 + tx;
#pragma unroll
        for (int i = ty; i < 32; i += 8)
            O[(blockIdx.x * 32 + i) * Hq + ox] = __float2bfloat16_rn(t[tx][i]);
    }
}

// ---------------- one-pass LayerNorm (128 thr/row, single barrier) ----------------
__global__ __launch_bounds__(128) void ln_k(
    const float* __restrict__ in, const float* __restrict__ gamma,
    const float* __restrict__ beta, float* __restrict__ out)
{
    __shared__ float s1[4], s2[4];
    const long long row = blockIdx.x;
    const int t = threadIdx.x;
    const float* p = in + row * Dq + t * 4;
    float4 v = *(const float4*)p;
    float s = v.x + v.y + v.z + v.w;
    float q = v.x * v.x + v.y * v.y + v.z * v.z + v.w * v.w;
#pragma unroll
    for (int off = 16; off > 0; off >>= 1) {
        s += __shfl_xor_sync(0xFFFFFFFF, s, off);
        q += __shfl_xor_sync(0xFFFFFFFF, q, off);
    }
    if ((t & 31) == 0) { s1[t >> 5] = s; s2[t >> 5] = q; }
    __syncthreads();
    const float sum = s1[0] + s1[1] + s1[2] + s1[3];
    const float sq  = s2[0] + s2[1] + s2[2] + s2[3];
    const float mu  = sum * (1.f / Dq);
    const float var = sq * (1.f / Dq) - mu * mu;
    const float inv = rsqrtf(var + 1e-5f);
    float4 g = *(const float4*)(gamma + t * 4);
    float4 b = *(const float4*)(beta + t * 4);
    float4 o;
    o.x = (v.x - mu) * inv * g.x + b.x;
    o.y = (v.y - mu) * inv * g.y + b.y;
    o.z = (v.z - mu) * inv * g.z + b.z;
    o.w = (v.w - mu) * inv * g.w + b.w;
    *(float4*)(out + row * Dq + t * 4) = o;
}

// ---------------- launch ----------------
extern "C" void kernel_launch(void* const* d_in, const int* in_sizes, int n_in,
                              void* d_out, int out_size)
{
    const float* X   = (const float*)d_in[0];
    const float* Wq  = (const float*)d_in[1];
    const float* bqp = (const float*)d_in[2];
    const float* Wk  = (const float*)d_in[3];
    const float* Wv  = (const float*)d_in[5];
    const float* bvp = (const float*)d_in[6];
    const float* Wo  = (const float*)d_in[7];
    const float* bop = (const float*)d_in[8];
    const float* ga  = (const float*)d_in[9];
    const float* be  = (const float*)d_in[10];
    float* out = (float*)d_out;

    void *px8, *py8, *pu8T, *pe8, *prs, *pwb, *pwpp8, *pwp8, *pg1, *pc2s, *pb2, *ptmp;
    cudaGetSymbolAddress(&px8, g_x8);
    cudaGetSymbolAddress(&py8, g_y8);
    cudaGetSymbolAddress(&pu8T, g_u8T);
    cudaGetSymbolAddress(&pe8, g_e8);
    cudaGetSymbolAddress(&prs, g_rs);
    cudaGetSymbolAddress(&pwb, g_wb);
    cudaGetSymbolAddress(&pwpp8, g_wpp8);
    cudaGetSymbolAddress(&pwp8, g_wp8);
    cudaGetSymbolAddress(&pg1, g_g1);
    cudaGetSymbolAddress(&pc2s, g_c2s);
    cudaGetSymbolAddress(&pb2, g_bias2);
    cudaGetSymbolAddress(&ptmp, g_tmp);
    uint8_t* x8   = (uint8_t*)px8;
    uint8_t* y8   = (uint8_t*)py8;
    uint8_t* u8T  = (uint8_t*)pu8T;
    uint8_t* e8   = (uint8_t*)pe8;
    float*   rs   = (float*)prs;
    __nv_bfloat16* wb = (__nv_bfloat16*)pwb;
    uint8_t* wpp8 = (uint8_t*)pwpp8;
    uint8_t* wp8  = (uint8_t*)pwp8;
    float*   g1   = (float*)pg1;
    float*   c2s  = (float*)pc2s;
    float*   b2   = (float*)pb2;
    float*   tmp  = (float*)ptmp;
    __nv_bfloat16* Wq_b  = wb;
    __nv_bfloat16* Wk_b  = wb + (size_t)Dq * Hq;
    __nv_bfloat16* Wv_b  = wb + (size_t)2 * Dq * Hq;
    __nv_bfloat16* WoT_b = wb + (size_t)3 * Dq * Hq;

    cudaFuncSetAttribute(mma_gemm_w2,     cudaFuncAttributeMaxDynamicSharedMemorySize, SMEM_TOTAL);
    cudaFuncSetAttribute(mma_gemm_f8_yu,  cudaFuncAttributeMaxDynamicSharedMemorySize, SMEM_TOTAL);
    cudaFuncSetAttribute(mma_gemm_f8<1>,  cudaFuncAttributeMaxDynamicSharedMemorySize, SMEM_TOTAL);
    cudaFuncSetAttribute(mma_gemm_f8<2>,  cudaFuncAttributeMaxDynamicSharedMemorySize, SMEM_TOTAL);

    const float inv_sqrt_h = 0.04419417382415922f;  // 1/sqrt(512)
    dim3 blk(256);

    // 0. prep (3 launches)
    gemv2_k<<<dim3(512, 2), 128>>>(Wk, bqp, Wo, bvp, bop, g1, b2);
    cvt_x8_c2_k<<<ROWS / 2, blk>>>(X, g1, x8, c2s, rs);
    wprep_k<<<dim3(16, 16, 4), blk>>>(Wq, Wk, Wv, Wo, wb);

    // 1. batched weight products: z=0 W''T*16 = 16*(Wk_b @ Wq_b^T); z=1 W'T*16 = 16*(WoT_b @ Wv_b^T)
    mma_gemm_w2<<<dim3(4, 4, 2), blk, SMEM_TOTAL>>>(Wk_b, Wq_b, wpp8,
                                                    WoT_b, Wv_b, wp8);
    // 2. batched y + u
    mma_gemm_f8_yu<<<dim3(4, 128, 2), blk, SMEM_TOTAL>>>(x8, wpp8, wp8, y8, u8T);
    // 3. e8 = fp8(8*exp(y8 @ x8^T / sqrt(H) + c2s[m])); rs += row sums
    mma_gemm_f8<1><<<dim3(Nq / 128, Nq / 128, Bq), blk, SMEM_TOTAL>>>(
        y8, x8, e8, rs, c2s, nullptr, nullptr,
        Dq, Dq, Dq, Nq,
        (long long)Nq * Dq, (long long)Nq * Dq, (long long)Nq * Nq, inv_sqrt_h);
    // 4. tmp = (e8 @ u8T)/rs + bias2[col] + X   [final pre-LN, fp32]
    mma_gemm_f8<2><<<dim3(Dq / 128, Nq / 128, Bq), blk, SMEM_TOTAL>>>(
        e8, u8T, tmp, rs, nullptr, b2, X,
        Nq, Nq, ROWS, Dq,
        (long long)Nq * Nq, (long long)Nq, (long long)Nq * Dq, 1.f);
    // 5. LayerNorm
    ln_k<<<ROWS, 128>>>(tmp, ga, be, out);
}